// round 13
// baseline (speedup 1.0000x reference)
#include <cuda_runtime.h>
#include <cuda_fp16.h>
#include <math.h>
#include <stdint.h>

// ---------------- problem constants ----------------
#define CN   2048
#define CN2  4096
#define CNY  16
#define CL   8
#define CD   768
#define CNIN 6144
#define CH   512
#define CNH  4096
#define CG   64
#define CV   50257
#define PSPLIT 16
#define LOSCALE 1024.0f
#define INVLOSCALE (1.0f / 1024.0f)

// ---------------- device scratch ----------------
__device__ __align__(16) __half g_eh[CN2 * CNIN];
__device__ __align__(16) __half g_el[CN2 * CNIN];     // lo * 1024
__device__ __align__(16) __half g_h1h[CN2 * CH];
__device__ __align__(16) __half g_h1l[CN2 * CH];      // lo * 1024
__device__ __align__(16) __half g_h2h[CN2 * CH];
__device__ __align__(16) __half g_h2l[CN2 * CH];      // lo * 1024
__device__ __align__(16) __half g_W1h[CH * CNIN];
__device__ __align__(16) __half g_W2h[CH * CH];
__device__ __align__(16) __half g_W3h[CNH * CH];
__device__ __align__(16) float g_X [CN2 * CNH];
__device__ __align__(16) float g_xmul[CNH];
__device__ __align__(16) float g_Yc[CN * CNY];
__device__ __align__(16) float g_ymul[CNY];
__device__ __align__(16) float g_bmean[CNY];
__device__ __align__(16) float g_ycss[CNY];
__device__ __align__(16) float g_scal[2];
__device__ __align__(16) float g_Mpart[4][CG * 64 * 64];
__device__ __align__(16) float g_apart[8][CNH * CNY];
__device__ __align__(16) float g_cov [CG * 64 * 64];
__device__ __align__(16) float g_covv[CG * 64 * 64];
__device__ __align__(16) float g_S[CG];
__device__ __align__(16) float g_w0[CNH * CNY];
__device__ __align__(16) float g_cw[CNH * CNY];
__device__ __align__(16) float g_p [CG * CNY];
__device__ __align__(16) float g_w [CNH * CNY];
__device__ __align__(16) float g_accp[PSPLIT][CN * CNY];
__device__ __align__(16) float g_vp  [PSPLIT][CN * CNY];
__device__ int g_tok64;

// ---------------- small kernels ----------------
__global__ void k_detect(const int* __restrict__ t, int n_elems) {
    __shared__ int nz;
    if (threadIdx.x == 0) nz = 0;
    __syncthreads();
    int local = 0;
    for (int i = 2 * threadIdx.x + 1; i < n_elems; i += 2 * 256)
        if (t[i] != 0) local = 1;
    if (local) atomicOr(&nz, 1);
    __syncthreads();
    if (threadIdx.x == 0) g_tok64 = (nz == 0) ? 1 : 0;
}

__global__ void k_scal(const float* __restrict__ rp, const float* __restrict__ tp) {
    g_scal[0] = expf(rp[0]) + 1e-8f;
    g_scal[1] = expf(tp[0]) + 1e-8f;
}

__global__ void k_ystats(const float* __restrict__ y) {
    int j = blockIdx.x, tid = threadIdx.x;
    __shared__ float red[256];
    __shared__ float sh_ym, sh_b;
    float s = 0.f, ss = 0.f;
    for (int n = tid; n < CN; n += 256) { float v = y[n * CNY + j]; s += v; ss += v * v; }
    red[tid] = s; __syncthreads();
    for (int st = 128; st; st >>= 1) { if (tid < st) red[tid] += red[tid + st]; __syncthreads(); }
    float S = red[0]; __syncthreads();
    red[tid] = ss; __syncthreads();
    for (int st = 128; st; st >>= 1) { if (tid < st) red[tid] += red[tid + st]; __syncthreads(); }
    float SS = red[0]; __syncthreads();
    if (tid == 0) {
        float var = (SS - S * S / (float)CN) / (float)(CN - 1);
        float ym = sqrtf(fmaxf(var, 0.f)) + 0.1f;
        float b = (S / (float)CN) / ym;
        sh_ym = ym; sh_b = b;
        g_ymul[j] = ym; g_bmean[j] = b;
    }
    __syncthreads();
    float ym = sh_ym, b = sh_b;
    float cs = 0.f;
    for (int n = tid; n < CN; n += 256) {
        float v = y[n * CNY + j] / ym - b;
        g_Yc[n * CNY + j] = v;
        cs += v * v;
    }
    red[tid] = cs; __syncthreads();
    for (int st = 128; st; st >>= 1) { if (tid < st) red[tid] += red[tid + st]; __syncthreads(); }
    if (tid == 0) g_ycss[j] = red[0];
}

// ---------------- fp16 split helper (lo scaled by 1024) ----------------
__device__ __forceinline__ void split2hs(float x, __half& h, __half& l) {
    h = __float2half_rn(x);
    l = __float2half_rn((x - __half2float(h)) * LOSCALE);
}

// weight convert (hi only)
#define NW1 (CH * CNIN / 4)
#define NW2 (CH * CH / 4)
#define NW3 (CNH * CH / 4)
__global__ void k_wh(const float4* __restrict__ W1, const float4* __restrict__ W2,
                     const float4* __restrict__ W3) {
    int idx = blockIdx.x * 256 + threadIdx.x;
    const float4* src; __half* dh; int li;
    if (idx < NW1)            { src = W1; dh = g_W1h; li = idx; }
    else if (idx < NW1 + NW2) { src = W2; dh = g_W2h; li = idx - NW1; }
    else if (idx < NW1 + NW2 + NW3) { src = W3; dh = g_W3h; li = idx - NW1 - NW2; }
    else return;
    float4 v = src[li];
    ((__half2*)dh)[li*2+0] = __halves2half2(__float2half_rn(v.x), __float2half_rn(v.y));
    ((__half2*)dh)[li*2+1] = __halves2half2(__float2half_rn(v.z), __float2half_rn(v.w));
}

// merged gather -> split fp16 (lo scaled)
__global__ void k_gather(const void* __restrict__ tokx, const void* __restrict__ tokq,
                         const float4* __restrict__ we4,
                         __half* __restrict__ eh, __half* __restrict__ el) {
    int idx = blockIdx.x * 256 + threadIdx.x;
    if (idx >= CN2 * (CNIN / 4)) return;
    int r = idx / (CNIN / 4), k4 = idx - r * (CNIN / 4);
    int l = k4 / (CD / 4), c4 = k4 - l * (CD / 4);
    const void* tok = (r < CN) ? tokx : tokq;
    int rr = (r < CN) ? r : r - CN;
    long long t;
    if (g_tok64) t = ((const long long*)tok)[rr * CL + l];
    else         t = (long long)((const int*)tok)[rr * CL + l];
    if (t < 0) t = 0;
    if (t >= CV) t = CV - 1;
    float4 v = we4[(size_t)t * (CD / 4) + c4];
    __half h0,l0,h1,l1,h2,l2,h3,l3;
    split2hs(v.x,h0,l0); split2hs(v.y,h1,l1); split2hs(v.z,h2,l2); split2hs(v.w,h3,l3);
    ((__half2*)eh)[idx*2+0] = __halves2half2(h0,h1);
    ((__half2*)eh)[idx*2+1] = __halves2half2(h2,h3);
    ((__half2*)el)[idx*2+0] = __halves2half2(l0,l1);
    ((__half2*)el)[idx*2+1] = __halves2half2(l2,l3);
}

// ---------------- asymmetric split-fp16 tensor-core GEMM (templated BM) -------
// C = A@B^T; hi pass: f32-accum HMMA; lo pass (A_lo*1024): f16-accum HMMA,
// epilogue adds lo/1024. Block BMx128, BK=32, 256 thr, warp (BM/2)x32.
// 2-stage cp.async ring, occ 2/SM.
template<int BM>
__global__ __launch_bounds__(256, 2) void k_gemm_fp16(
    const __half* __restrict__ Ah, const __half* __restrict__ Al,
    const __half* __restrict__ Bh,
    const float* __restrict__ bias,
    float* __restrict__ Cf, __half* __restrict__ Ch, __half* __restrict__ Cl,
    int M, int Nn, int K, int mode)
{
    constexpr int MT   = BM / 32;
    constexpr int ABYT = BM * 128;
    constexpr int STG  = ABYT + 8192;
    constexpr int ACH  = BM * 8;
    constexpr int ITER = (ACH + 512) / 256;
    extern __shared__ __align__(16) char smem[];
    const uint32_t sbase = (uint32_t)__cvta_generic_to_shared(smem);
    const int tid = threadIdx.x;
    const int lane = tid & 31, wid = tid >> 5;
    const int warp_m = wid >> 2, warp_n = wid & 3;
    const int m0 = blockIdx.y * BM, n0 = blockIdx.x * 128;
    const int KT = K >> 5;

    float c[MT][4][4];
    uint32_t cl[MT][4][2];
#pragma unroll
    for (int i = 0; i < MT; ++i)
#pragma unroll
        for (int j = 0; j < 4; ++j) {
#pragma unroll
            for (int r = 0; r < 4; ++r) c[i][j][r] = 0.f;
            cl[i][j][0] = 0u; cl[i][j][1] = 0u;
        }

    auto load_tile = [&](int kt, int stage) {
        int k0 = kt << 5;
        uint32_t sb = sbase + stage * STG;
#pragma unroll
        for (int i = 0; i < ITER; ++i) {
            int id = tid + (i << 8);
            const __half* g;
            uint32_t sa;
            if (id < ACH) {
                int r = id >> 3, ck = id & 7;
                const __half* src = (ck < 4) ? Ah : Al;
                g = src + (size_t)(m0 + r) * K + k0 + (ck & 3) * 8;
                sa = sb + r * 128 + ((ck ^ (r & 7)) << 4);
            } else {
                int j = id - ACH;
                int r = j >> 2, ck = j & 3;
                g = Bh + (size_t)(n0 + r) * K + k0 + ck * 8;
                sa = sb + ABYT + r * 64 + ((ck ^ ((r >> 1) & 3)) << 4);
            }
            asm volatile("cp.async.cg.shared.global [%0], [%1], 16;\n" :: "r"(sa), "l"(g));
        }
        asm volatile("cp.async.commit_group;\n");
    };

    if (KT > 0) load_tile(0, 0);

    for (int kt = 0; kt < KT; ++kt) {
        if (kt + 1 < KT) {
            load_tile(kt + 1, (kt + 1) & 1);
            asm volatile("cp.async.wait_group 1;\n");
        } else {
            asm volatile("cp.async.wait_group 0;\n");
        }
        __syncthreads();
        uint32_t sb = sbase + (kt & 1) * STG;

#pragma unroll
        for (int s16 = 0; s16 < 2; ++s16) {
            uint32_t bhf[4][2];
#pragma unroll
            for (int nt = 0; nt < 4; ++nt) {
                int r = warp_n * 32 + nt * 8 + (lane & 7);
                int ck = 2 * s16 + ((lane >> 3) & 1);
                uint32_t b1 = sb + ABYT + r * 64 + ((ck ^ ((r >> 1) & 3)) << 4);
                asm volatile("ldmatrix.sync.aligned.m8n8.x2.shared.b16 {%0,%1}, [%2];"
                    : "=r"(bhf[nt][0]), "=r"(bhf[nt][1]) : "r"(b1));
            }
#pragma unroll
            for (int mt = 0; mt < MT; ++mt) {
                int r = warp_m * (BM / 2) + mt * 16 + (lane & 15);
                int sw = r & 7;
                int ckh = 2 * s16 + (lane >> 4);
                uint32_t a1 = sb + r * 128 + ((ckh ^ sw) << 4);
                uint32_t a2 = sb + r * 128 + (((ckh + 4) ^ sw) << 4);
                uint32_t ahf[4], alf[4];
                asm volatile("ldmatrix.sync.aligned.m8n8.x4.shared.b16 {%0,%1,%2,%3}, [%4];"
                    : "=r"(ahf[0]), "=r"(ahf[1]), "=r"(ahf[2]), "=r"(ahf[3]) : "r"(a1));
                asm volatile("ldmatrix.sync.aligned.m8n8.x4.shared.b16 {%0,%1,%2,%3}, [%4];"
                    : "=r"(alf[0]), "=r"(alf[1]), "=r"(alf[2]), "=r"(alf[3]) : "r"(a2));
#pragma unroll
                for (int nt = 0; nt < 4; ++nt) {
                    // hi pass: f32 accum
                    asm volatile("mma.sync.aligned.m16n8k16.row.col.f32.f16.f16.f32 "
                        "{%0,%1,%2,%3}, {%4,%5,%6,%7}, {%8,%9}, {%0,%1,%2,%3};"
                        : "+f"(c[mt][nt][0]), "+f"(c[mt][nt][1]),
                          "+f"(c[mt][nt][2]), "+f"(c[mt][nt][3])
                        : "r"(ahf[0]), "r"(ahf[1]), "r"(ahf[2]), "r"(ahf[3]),
                          "r"(bhf[nt][0]), "r"(bhf[nt][1]));
                    // lo pass: f16 accum (values pre-scaled by 1024)
                    asm volatile("mma.sync.aligned.m16n8k16.row.col.f16.f16.f16.f16 "
                        "{%0,%1}, {%2,%3,%4,%5}, {%6,%7}, {%0,%1};"
                        : "+r"(cl[mt][nt][0]), "+r"(cl[mt][nt][1])
                        : "r"(alf[0]), "r"(alf[1]), "r"(alf[2]), "r"(alf[3]),
                          "r"(bhf[nt][0]), "r"(bhf[nt][1]));
                }
            }
        }
        __syncthreads();
    }

    // epilogue
#pragma unroll
    for (int mt = 0; mt < MT; ++mt) {
        int row = m0 + warp_m * (BM / 2) + mt * 16 + (lane >> 2);
#pragma unroll
        for (int nt = 0; nt < 4; ++nt) {
            int col = n0 + warp_n * 32 + nt * 8 + 2 * (lane & 3);
            float b0 = bias[col], b1 = bias[col + 1];
            float2 lo01 = __half22float2(*(__half2*)&cl[mt][nt][0]);
            float2 lo23 = __half22float2(*(__half2*)&cl[mt][nt][1]);
            float v0 = c[mt][nt][0] + lo01.x * INVLOSCALE + b0;
            float v1 = c[mt][nt][1] + lo01.y * INVLOSCALE + b1;
            float v2 = c[mt][nt][2] + lo23.x * INVLOSCALE + b0;
            float v3 = c[mt][nt][3] + lo23.y * INVLOSCALE + b1;
            if (mode == 1) {
                v0 = fmaxf(v0, 0.f); v1 = fmaxf(v1, 0.f);
                v2 = fmaxf(v2, 0.f); v3 = fmaxf(v3, 0.f);
                __half h0,l0,h1,l1,h2,l2,h3,l3;
                split2hs(v0,h0,l0); split2hs(v1,h1,l1); split2hs(v2,h2,l2); split2hs(v3,h3,l3);
                *(__half2*)&Ch[(size_t)row * Nn + col] = __halves2half2(h0, h1);
                *(__half2*)&Cl[(size_t)row * Nn + col] = __halves2half2(l0, l1);
                *(__half2*)&Ch[(size_t)(row + 8) * Nn + col] = __halves2half2(h2, h3);
                *(__half2*)&Cl[(size_t)(row + 8) * Nn + col] = __halves2half2(l2, l3);
            } else {
                *(float2*)&Cf[(size_t)row * Nn + col] = make_float2(v0, v1);
                *(float2*)&Cf[(size_t)(row + 8) * Nn + col] = make_float2(v2, v3);
            }
        }
    }
}

// ---------------- per-column std of X (train rows) -> xmul ----------------
__global__ void k_xstats() {
    int c = blockIdx.x * 256 + threadIdx.x;
    float s[8] = {}, ss[8] = {};
    for (int n = 0; n < CN; n += 8) {
#pragma unroll
        for (int u = 0; u < 8; ++u) {
            float v = g_X[(size_t)(n + u) * CNH + c];
            s[u] += v; ss[u] += v * v;
        }
    }
    double S = 0.0, SS = 0.0;
#pragma unroll
    for (int u = 0; u < 8; ++u) { S += (double)s[u]; SS += (double)ss[u]; }
    double var = (SS - S * S / (double)CN) / (double)(CN - 1);
    if (var < 0.0) var = 0.0;
    g_xmul[c] = (float)sqrt(var) + 0.1f;
}

// ---------------- Gram partials (xmul folded) ----------------
__global__ __launch_bounds__(256) void k_cov() {
    int g = blockIdx.x, sp = blockIdx.y, tid = threadIdx.x;
    __shared__ float tile[32][68];
    __shared__ float xminv[64];
    if (tid < 64) xminv[tid] = 1.0f / g_xmul[g * 64 + tid];
    __syncthreads();
    const int ti = (tid & 15) * 4, tj = (tid >> 4) * 4;
    float acc[4][4] = {};
    for (int n0 = sp * 512; n0 < sp * 512 + 512; n0 += 32) {
#pragma unroll
        for (int it = 0; it < 2; ++it) {
            int idx = tid + it * 256;
            int r = idx >> 4, c4 = idx & 15;
            float4 v = *(const float4*)&g_X[(size_t)(n0 + r) * CNH + g * 64 + c4 * 4];
            v.x *= xminv[c4*4+0]; v.y *= xminv[c4*4+1];
            v.z *= xminv[c4*4+2]; v.w *= xminv[c4*4+3];
            *(float4*)&tile[r][c4 * 4] = v;
        }
        __syncthreads();
#pragma unroll 4
        for (int r = 0; r < 32; ++r) {
            float xi[4], xj[4];
            *(float4*)xi = *(const float4*)&tile[r][ti];
            *(float4*)xj = *(const float4*)&tile[r][tj];
#pragma unroll
            for (int a = 0; a < 4; ++a)
#pragma unroll
                for (int b = 0; b < 4; ++b)
                    acc[a][b] = fmaf(xi[a], xj[b], acc[a][b]);
        }
        __syncthreads();
    }
    float* out = &g_Mpart[sp][g * 4096];
#pragma unroll
    for (int a = 0; a < 4; ++a)
#pragma unroll
        for (int b = 0; b < 4; ++b)
            out[(ti + a) * 64 + (tj + b)] = acc[a][b];
}

// ---------------- a partials (xmul folded) ----------------
__global__ __launch_bounds__(256) void k_apart() {
    int c = blockIdx.x * 256 + threadIdx.x;
    int sp = blockIdx.y;
    int n0 = sp * 256;
    __shared__ float ys[256 * CNY];
    for (int i = threadIdx.x; i < 256 * CNY; i += 256) ys[i] = g_Yc[n0 * CNY + i];
    __syncthreads();
    float xinv = 1.0f / g_xmul[c];
    float acc[CNY] = {};
    for (int n = 0; n < 256; ++n) {
        float v = g_X[(size_t)(n0 + n) * CNH + c] * xinv;
#pragma unroll
        for (int j = 0; j < CNY; ++j) acc[j] = fmaf(v, ys[n * CNY + j], acc[j]);
    }
#pragma unroll
    for (int j = 0; j < CNY; ++j) g_apart[sp][c * CNY + j] = acc[j];
}

// ---------------- Cholesky + logdet + inverse ----------------
__global__ __launch_bounds__(64) void k_chol() {
    int g = blockIdx.x, tid = threadIdx.x;
    __shared__ float A[64][65];
    __shared__ float Yv[64][64];
    float rg = g_scal[0], t = g_scal[1];
    for (int i = 0; i < 64; ++i) {
        float m = 0.f;
#pragma unroll
        for (int sp = 0; sp < 4; ++sp) m += g_Mpart[sp][g * 4096 + i * 64 + tid];
        A[i][tid] = t * m + (i == tid ? rg : 0.f);
    }
    __syncthreads();
    for (int k = 0; k < 64; ++k) {
        float akk = A[k][k];
        float skk = sqrtf(akk);
        __syncthreads();
        if (tid == k) A[k][k] = skk;
        else if (tid > k) A[tid][k] = A[tid][k] / skk;
        __syncthreads();
        if (tid > k) {
            float lik = A[tid][k];
            for (int j = k + 1; j <= tid; ++j) A[tid][j] -= lik * A[j][k];
        }
        __syncthreads();
    }
    if (tid == 0) {
        float s = 0.f;
        for (int i = 0; i < 64; ++i) s += logf(A[i][i]);
        g_S[g] = 2.f * s;
    }
    const int c = tid;
    for (int i = 0; i < 64; ++i) {
        if (i < c) { Yv[i][c] = 0.f; continue; }
        float s = (i == c) ? 1.f : 0.f;
        for (int j = c; j < i; ++j) s -= A[i][j] * Yv[j][c];
        Yv[i][c] = s / A[i][i];
    }
    for (int i = 63; i >= 0; --i) {
        float s = Yv[i][c];
        for (int j = i + 1; j < 64; ++j) s -= A[j][i] * Yv[j][c];
        Yv[i][c] = s / A[i][i];
    }
    __syncthreads();
    for (int i = 0; i < 64; ++i) g_cov[g * 4096 + i * 64 + c] = Yv[i][c];
}

// ---------------- w0, cw ----------------
__global__ __launch_bounds__(256) void k_w0cw() {
    int g = blockIdx.x, tid = threadIdx.x;
    __shared__ float covs[64][65];
    __shared__ float as[64][17];
    __shared__ float w0s[64][17];
    for (int idx = tid; idx < 4096; idx += 256)
        covs[idx >> 6][idx & 63] = g_cov[g * 4096 + idx];
    for (int idx = tid; idx < 64 * CNY; idx += 256) {
        int i = idx >> 4, j = idx & 15;
        float s = 0.f;
#pragma unroll
        for (int sp = 0; sp < 8; ++sp) s += g_apart[sp][(g * 64 + i) * CNY + j];
        as[i][j] = s;
    }
    __syncthreads();
    float t = g_scal[1];
    int j = tid & 15, i0 = (tid >> 4) * 4;
#pragma unroll
    for (int ii = 0; ii < 4; ++ii) {
        float s = 0.f;
        for (int k = 0; k < 64; ++k) s = fmaf(covs[i0 + ii][k], as[k][j], s);
        w0s[i0 + ii][j] = t * s;
    }
    __syncthreads();
#pragma unroll
    for (int ii = 0; ii < 4; ++ii) {
        float s = 0.f;
        for (int k = 0; k < 64; ++k) s = fmaf(covs[i0 + ii][k], w0s[k][j], s);
        g_cw[(g * 64 + i0 + ii) * CNY + j] = s;
        g_w0[(g * 64 + i0 + ii) * CNY + j] = w0s[i0 + ii][j];
    }
}

// ---------------- softmax over groups ----------------
__global__ __launch_bounds__(1024) void k_p() {
    int tid = threadIdx.x;
    int g = tid >> 4, j = tid & 15;
    float corr = 0.f;
    for (int i = 0; i < 64; ++i)
        corr = fmaf(g_w0[(g * 64 + i) * CNY + j], g_cw[(g * 64 + i) * CNY + j], corr);
    float t = g_scal[1];
    float lg = corr - t * g_ycss[j] - g_S[g];
    __shared__ float L[64][17];
    __shared__ float mx[16], sm[16];
    L[g][j] = lg;
    __syncthreads();
    if (tid < 16) {
        float m = -1e30f;
        for (int gg = 0; gg < 64; ++gg) m = fmaxf(m, L[gg][tid]);
        float s = 0.f;
        for (int gg = 0; gg < 64; ++gg) s += expf(L[gg][tid] - m);
        mx[tid] = m; sm[tid] = s;
    }
    __syncthreads();
    g_p[g * CNY + j] = expf(lg - mx[j]) / sm[j];
}

// ---------------- fold xmul into w and cov (merged) ----------------
__global__ void k_fold() {
    int idx = blockIdx.x * 256 + threadIdx.x;
    if (idx < CNH * CNY) {
        int c = idx >> 4, j = idx & 15;
        g_w[idx] = g_w0[idx] * g_p[(c >> 6) * CNY + j] / g_xmul[c];
    }
    int g = idx >> 12, i = (idx >> 6) & 63, j = idx & 63;
    g_covv[idx] = g_cov[idx] / (g_xmul[g * 64 + i] * g_xmul[g * 64 + j]);
}

// ---------------- predict partials: groups split PSPLIT ways ----------------
__global__ __launch_bounds__(128) void k_predict_part(const float* __restrict__ XQ) {
    const int tid = threadIdx.x;
    const int r = tid >> 3, lane = tid & 7;
    const int row0 = blockIdx.x * 16;
    const int g0 = blockIdx.y * (CG / PSPLIT);
    __shared__ float Xs[16][65];
    __shared__ float Cs[64][65];
    __shared__ float Ws[64][17];
    __shared__ float ps[16];
    float accy[CNY] = {};
    float v0 = 0.f, v1 = 0.f;
    for (int g = g0; g < g0 + CG / PSPLIT; ++g) {
#pragma unroll
        for (int it = 0; it < 8; ++it) {
            int idx = tid + it * 128;
            Xs[idx >> 6][idx & 63] = XQ[(size_t)(row0 + (idx >> 6)) * CNH + g * 64 + (idx & 63)];
        }
#pragma unroll
        for (int it = 0; it < 32; ++it) {
            int idx = tid + it * 128;
            Cs[idx >> 6][idx & 63] = g_covv[g * 4096 + idx];
        }
#pragma unroll
        for (int it = 0; it < 8; ++it) {
            int idx = tid + it * 128;
            Ws[idx >> 4][idx & 15] = g_w[(g * 64 + (idx >> 4)) * CNY + (idx & 15)];
        }
        if (tid < 16) ps[tid] = g_p[g * CNY + tid];
        __syncthreads();
        float x[8];
#pragma unroll
        for (int ii = 0; ii < 8; ++ii) x[ii] = Xs[r][lane * 8 + ii];
#pragma unroll
        for (int ii = 0; ii < 8; ++ii)
#pragma unroll
            for (int j = 0; j < CNY; ++j)
                accy[j] = fmaf(x[ii], Ws[lane * 8 + ii][j], accy[j]);
        float s = 0.f;
        for (int jc = 0; jc < 64; ++jc) {
            float xj = Xs[r][jc];
            float q = 0.f;
#pragma unroll
            for (int ii = 0; ii < 8; ++ii) q = fmaf(Cs[lane * 8 + ii][jc], x[ii], q);
            s = fmaf(q, xj, s);
        }
        s += __shfl_xor_sync(0xffffffffu, s, 4);
        s += __shfl_xor_sync(0xffffffffu, s, 2);
        s += __shfl_xor_sync(0xffffffffu, s, 1);
        v0 = fmaf(s, ps[lane * 2 + 0], v0);
        v1 = fmaf(s, ps[lane * 2 + 1], v1);
        __syncthreads();
    }
#pragma unroll
    for (int j = 0; j < CNY; ++j) {
        accy[j] += __shfl_xor_sync(0xffffffffu, accy[j], 4);
        accy[j] += __shfl_xor_sync(0xffffffffu, accy[j], 2);
        accy[j] += __shfl_xor_sync(0xffffffffu, accy[j], 1);
    }
    const int row = row0 + r;
    const int j0 = lane * 2, j1 = j0 + 1;
    g_accp[blockIdx.y][row * CNY + j0] = accy[j0];
    g_accp[blockIdx.y][row * CNY + j1] = accy[j1];
    g_vp[blockIdx.y][row * CNY + j0] = v0;
    g_vp[blockIdx.y][row * CNY + j1] = v1;
}

// ---------------- predict combine ----------------
__global__ void k_predict_comb(float* __restrict__ out) {
    int idx = blockIdx.x * 256 + threadIdx.x;
    int j = idx & 15;
    float a = 0.f, v = 0.f;
#pragma unroll
    for (int s = 0; s < PSPLIT; ++s) { a += g_accp[s][idx]; v += g_vp[s][idx]; }
    out[idx] = (a + g_bmean[j]) * g_ymul[j];
    out[CN * CNY + idx] = sqrtf(fmaxf(v, 0.f)) * g_ymul[j];
}

// ---------------- launcher ----------------
extern "C" void kernel_launch(void* const* d_in, const int* in_sizes, int n_in,
                              void* d_out, int out_size) {
    const void* x  = d_in[0];
    const float* y = (const float*)d_in[1];
    const void* qx = d_in[2];
    const float* we = (const float*)d_in[3];
    const float* W1 = (const float*)d_in[4];
    const float* b1 = (const float*)d_in[5];
    const float* W2 = (const float*)d_in[6];
    const float* b2 = (const float*)d_in[7];
    const float* W3 = (const float*)d_in[8];
    const float* b3 = (const float*)d_in[9];
    const float* rp = (const float*)d_in[10];
    const float* tp = (const float*)d_in[11];
    float* out = (float*)d_out;

    __half *peh, *pel, *ph1h, *ph1l, *ph2h, *ph2l;
    __half *pW1h, *pW2h, *pW3h;
    float *pX;
    cudaGetSymbolAddress((void**)&peh,  g_eh);
    cudaGetSymbolAddress((void**)&pel,  g_el);
    cudaGetSymbolAddress((void**)&ph1h, g_h1h);
    cudaGetSymbolAddress((void**)&ph1l, g_h1l);
    cudaGetSymbolAddress((void**)&ph2h, g_h2h);
    cudaGetSymbolAddress((void**)&ph2l, g_h2l);
    cudaGetSymbolAddress((void**)&pW1h, g_W1h);
    cudaGetSymbolAddress((void**)&pW2h, g_W2h);
    cudaGetSymbolAddress((void**)&pW3h, g_W3h);
    cudaGetSymbolAddress((void**)&pX,  g_X);
    float* pXQ = pX + (size_t)CN * CNH;

    const int SM64  = 2 * (64 * 128 + 8192);     // 32 KB
    cudaFuncSetAttribute((void*)k_gemm_fp16<64>,  cudaFuncAttributeMaxDynamicSharedMemorySize, SM64);

    // launches 1-3, captured launch (#4) is GEMM1
    k_detect<<<1, 256>>>((const int*)x, in_sizes[0]);
    k_wh<<<(NW1 + NW2 + NW3 + 255) / 256, 256>>>((const float4*)W1, (const float4*)W2, (const float4*)W3);
    const int gatherBlocks = (CN2 * (CNIN / 4) + 255) / 256;
    k_gather<<<gatherBlocks, 256>>>(x, qx, (const float4*)we, peh, pel);

    k_gemm_fp16<64><<<dim3(CH / 128, CN2 / 64), 256, SM64>>>(peh, pel, pW1h, b1, nullptr, ph1h, ph1l, CN2, CH, CNIN, 1);
    k_gemm_fp16<64><<<dim3(CH / 128, CN2 / 64), 256, SM64>>>(ph1h, ph1l, pW2h, b2, nullptr, ph2h, ph2l, CN2, CH, CH, 1);
    k_gemm_fp16<64><<<dim3(CNH / 128, CN2 / 64), 256, SM64>>>(ph2h, ph2l, pW3h, b3, pX, nullptr, nullptr, CN2, CNH, CH, 0);

    // ridge learn
    k_scal<<<1, 1>>>(rp, tp);
    k_ystats<<<16, 256>>>(y);
    k_xstats<<<CNH / 256, 256>>>();
    k_cov<<<dim3(CG, 4), 256>>>();
    k_apart<<<dim3(CNH / 256, 8), 256>>>();
    k_chol<<<CG, 64>>>();
    k_w0cw<<<CG, 256>>>();
    k_p<<<1, 1024>>>();
    k_fold<<<(CG * 64 * 64) / 256, 256>>>();

    // predict: group-split partials + combine
    k_predict_part<<<dim3(CN / 16, PSPLIT), 128>>>(pXQ);
    k_predict_comb<<<(CN * CNY) / 256, 256>>>(out);
}

// round 14
// speedup vs baseline: 1.0566x; 1.0566x over previous
#include <cuda_runtime.h>
#include <cuda_fp16.h>
#include <math.h>
#include <stdint.h>

// ---------------- problem constants ----------------
#define CN   2048
#define CN2  4096
#define CNY  16
#define CL   8
#define CD   768
#define CNIN 6144
#define CH   512
#define CNH  4096
#define CG   64
#define CV   50257
#define PSPLIT 8

// ---------------- device scratch ----------------
__device__ __align__(16) __half g_eh[CN2 * CNIN];
__device__ __align__(16) __half g_h1h[CN2 * CH];
__device__ __align__(16) __half g_h1l[CN2 * CH];
__device__ __align__(16) __half g_h2h[CN2 * CH];
__device__ __align__(16) __half g_h2l[CN2 * CH];
__device__ __align__(16) __half g_W1h[CH * CNIN];
__device__ __align__(16) __half g_W2h[CH * CH];
__device__ __align__(16) __half g_W3h[CNH * CH];
__device__ __align__(16) float g_X [CN2 * CNH];
__device__ __align__(16) float g_xmul[CNH];
__device__ __align__(16) float g_Yc[CN * CNY];
__device__ __align__(16) float g_ymul[CNY];
__device__ __align__(16) float g_bmean[CNY];
__device__ __align__(16) float g_ycss[CNY];
__device__ __align__(16) float g_scal[2];
__device__ __align__(16) float g_Mpart[4][CG * 64 * 64];
__device__ __align__(16) float g_apart[8][CNH * CNY];
__device__ __align__(16) float g_cov [CG * 64 * 64];
__device__ __align__(16) float g_covv[CG * 64 * 64];
__device__ __align__(16) float g_S[CG];
__device__ __align__(16) float g_w0[CNH * CNY];
__device__ __align__(16) float g_cw[CNH * CNY];
__device__ __align__(16) float g_p [CG * CNY];
__device__ __align__(16) float g_w [CNH * CNY];
__device__ __align__(16) float g_accp[PSPLIT][CN * CNY];
__device__ __align__(16) float g_vp  [PSPLIT][CN * CNY];
__device__ int g_tok64;

// ---------------- small kernels ----------------
__global__ void k_detect(const int* __restrict__ t, int n_elems) {
    __shared__ int nz;
    if (threadIdx.x == 0) nz = 0;
    __syncthreads();
    int local = 0;
    for (int i = 2 * threadIdx.x + 1; i < n_elems; i += 2 * 256)
        if (t[i] != 0) local = 1;
    if (local) atomicOr(&nz, 1);
    __syncthreads();
    if (threadIdx.x == 0) g_tok64 = (nz == 0) ? 1 : 0;
}

__global__ void k_scal(const float* __restrict__ rp, const float* __restrict__ tp) {
    g_scal[0] = expf(rp[0]) + 1e-8f;
    g_scal[1] = expf(tp[0]) + 1e-8f;
}

__global__ void k_ystats(const float* __restrict__ y) {
    int j = blockIdx.x, tid = threadIdx.x;
    __shared__ float red[256];
    __shared__ float sh_ym, sh_b;
    float s = 0.f, ss = 0.f;
    for (int n = tid; n < CN; n += 256) { float v = y[n * CNY + j]; s += v; ss += v * v; }
    red[tid] = s; __syncthreads();
    for (int st = 128; st; st >>= 1) { if (tid < st) red[tid] += red[tid + st]; __syncthreads(); }
    float S = red[0]; __syncthreads();
    red[tid] = ss; __syncthreads();
    for (int st = 128; st; st >>= 1) { if (tid < st) red[tid] += red[tid + st]; __syncthreads(); }
    float SS = red[0]; __syncthreads();
    if (tid == 0) {
        float var = (SS - S * S / (float)CN) / (float)(CN - 1);
        float ym = sqrtf(fmaxf(var, 0.f)) + 0.1f;
        float b = (S / (float)CN) / ym;
        sh_ym = ym; sh_b = b;
        g_ymul[j] = ym; g_bmean[j] = b;
    }
    __syncthreads();
    float ym = sh_ym, b = sh_b;
    float cs = 0.f;
    for (int n = tid; n < CN; n += 256) {
        float v = y[n * CNY + j] / ym - b;
        g_Yc[n * CNY + j] = v;
        cs += v * v;
    }
    red[tid] = cs; __syncthreads();
    for (int st = 128; st; st >>= 1) { if (tid < st) red[tid] += red[tid + st]; __syncthreads(); }
    if (tid == 0) g_ycss[j] = red[0];
}

// ---------------- fp16 split helper ----------------
__device__ __forceinline__ void split2h(float x, __half& h, __half& l) {
    h = __float2half_rn(x);
    l = __float2half_rn(x - __half2float(h));
}

// weight convert (hi only)
#define NW1 (CH * CNIN / 4)
#define NW2 (CH * CH / 4)
#define NW3 (CNH * CH / 4)
__global__ void k_wh(const float4* __restrict__ W1, const float4* __restrict__ W2,
                     const float4* __restrict__ W3) {
    int idx = blockIdx.x * 256 + threadIdx.x;
    const float4* src; __half* dh; int li;
    if (idx < NW1)            { src = W1; dh = g_W1h; li = idx; }
    else if (idx < NW1 + NW2) { src = W2; dh = g_W2h; li = idx - NW1; }
    else if (idx < NW1 + NW2 + NW3) { src = W3; dh = g_W3h; li = idx - NW1 - NW2; }
    else return;
    float4 v = src[li];
    ((__half2*)dh)[li*2+0] = __halves2half2(__float2half_rn(v.x), __float2half_rn(v.y));
    ((__half2*)dh)[li*2+1] = __halves2half2(__float2half_rn(v.z), __float2half_rn(v.w));
}

// merged gather -> fp16 hi only
__global__ void k_gather(const void* __restrict__ tokx, const void* __restrict__ tokq,
                         const float4* __restrict__ we4, __half* __restrict__ eh) {
    int idx = blockIdx.x * 256 + threadIdx.x;
    if (idx >= CN2 * (CNIN / 4)) return;
    int r = idx / (CNIN / 4), k4 = idx - r * (CNIN / 4);
    int l = k4 / (CD / 4), c4 = k4 - l * (CD / 4);
    const void* tok = (r < CN) ? tokx : tokq;
    int rr = (r < CN) ? r : r - CN;
    long long t;
    if (g_tok64) t = ((const long long*)tok)[rr * CL + l];
    else         t = (long long)((const int*)tok)[rr * CL + l];
    if (t < 0) t = 0;
    if (t >= CV) t = CV - 1;
    float4 v = we4[(size_t)t * (CD / 4) + c4];
    ((__half2*)eh)[idx*2+0] = __halves2half2(__float2half_rn(v.x), __float2half_rn(v.y));
    ((__half2*)eh)[idx*2+1] = __halves2half2(__float2half_rn(v.z), __float2half_rn(v.w));
}

// ---------------- asymmetric split-fp16 tensor-core GEMM ----------------
// C = A@B^T. LO=true: D += Ah*Bh + Al*Bh (split A). LO=false: D = Ah*Bh only.
// Block BMx128, BK=32, 256 thr, warp grid 2m x 4n, warp tile (BM/2)x32.
// 2-stage cp.async ring, occ 2 CTA/SM.
// LO=true:  A rows 128B = 8x16B {hi0..3, lo0..3}, phys = ck ^ (r&7).
// LO=false: A rows  64B = 4x16B hi,               phys = ck ^ ((r>>1)&3).
// B rows 64B = 4x16B hi, phys = ck ^ ((r>>1)&3).
template<int BM, bool LO>
__global__ __launch_bounds__(256, 2) void k_gemm_fp16(
    const __half* __restrict__ Ah, const __half* __restrict__ Al,
    const __half* __restrict__ Bh,
    const float* __restrict__ bias,
    float* __restrict__ Cf, __half* __restrict__ Ch, __half* __restrict__ Cl,
    int M, int Nn, int K, int mode)
{
    constexpr int MT    = BM / 32;
    constexpr int AROWB = LO ? 128 : 64;
    constexpr int ABYT  = BM * AROWB;
    constexpr int STG   = ABYT + 8192;
    constexpr int ACH   = BM * (AROWB / 16);
    constexpr int TCH   = ACH + 512;
    constexpr int ITER  = (TCH + 255) / 256;
    extern __shared__ __align__(16) char smem[];
    const uint32_t sbase = (uint32_t)__cvta_generic_to_shared(smem);
    const int tid = threadIdx.x;
    const int lane = tid & 31, wid = tid >> 5;
    const int warp_m = wid >> 2, warp_n = wid & 3;
    const int m0 = blockIdx.y * BM, n0 = blockIdx.x * 128;
    const int KT = K >> 5;

    float c[MT][4][4];
#pragma unroll
    for (int i = 0; i < MT; ++i)
#pragma unroll
        for (int j = 0; j < 4; ++j)
#pragma unroll
            for (int r = 0; r < 4; ++r) c[i][j][r] = 0.f;

    auto load_tile = [&](int kt, int stage) {
        int k0 = kt << 5;
        uint32_t sb = sbase + stage * STG;
#pragma unroll
        for (int i = 0; i < ITER; ++i) {
            int id = tid + (i << 8);
            if (id >= TCH) break;
            const __half* g;
            uint32_t sa;
            if (id < ACH) {
                if (LO) {
                    int r = id >> 3, ck = id & 7;
                    const __half* src = (ck < 4) ? Ah : Al;
                    g = src + (size_t)(m0 + r) * K + k0 + (ck & 3) * 8;
                    sa = sb + r * 128 + ((ck ^ (r & 7)) << 4);
                } else {
                    int r = id >> 2, ck = id & 3;
                    g = Ah + (size_t)(m0 + r) * K + k0 + ck * 8;
                    sa = sb + r * 64 + ((ck ^ ((r >> 1) & 3)) << 4);
                }
            } else {
                int j = id - ACH;
                int r = j >> 2, ck = j & 3;
                g = Bh + (size_t)(n0 + r) * K + k0 + ck * 8;
                sa = sb + ABYT + r * 64 + ((ck ^ ((r >> 1) & 3)) << 4);
            }
            asm volatile("cp.async.cg.shared.global [%0], [%1], 16;\n" :: "r"(sa), "l"(g));
        }
        asm volatile("cp.async.commit_group;\n");
    };

    if (KT > 0) load_tile(0, 0);

    for (int kt = 0; kt < KT; ++kt) {
        if (kt + 1 < KT) {
            load_tile(kt + 1, (kt + 1) & 1);
            asm volatile("cp.async.wait_group 1;\n");
        } else {
            asm volatile("cp.async.wait_group 0;\n");
        }
        __syncthreads();
        uint32_t sb = sbase + (kt & 1) * STG;

#pragma unroll
        for (int s16 = 0; s16 < 2; ++s16) {
            uint32_t bhf[4][2];
#pragma unroll
            for (int nt = 0; nt < 4; ++nt) {
                int r = warp_n * 32 + nt * 8 + (lane & 7);
                int ck = 2 * s16 + ((lane >> 3) & 1);
                uint32_t b1 = sb + ABYT + r * 64 + ((ck ^ ((r >> 1) & 3)) << 4);
                asm volatile("ldmatrix.sync.aligned.m8n8.x2.shared.b16 {%0,%1}, [%2];"
                    : "=r"(bhf[nt][0]), "=r"(bhf[nt][1]) : "r"(b1));
            }
#pragma unroll
            for (int mt = 0; mt < MT; ++mt) {
                int r = warp_m * (BM / 2) + mt * 16 + (lane & 15);
                int ckh = 2 * s16 + (lane >> 4);
                uint32_t ahf[4], alf[4];
                if (LO) {
                    int sw = r & 7;
                    uint32_t a1 = sb + r * 128 + ((ckh ^ sw) << 4);
                    uint32_t a2 = sb + r * 128 + (((ckh + 4) ^ sw) << 4);
                    asm volatile("ldmatrix.sync.aligned.m8n8.x4.shared.b16 {%0,%1,%2,%3}, [%4];"
                        : "=r"(ahf[0]), "=r"(ahf[1]), "=r"(ahf[2]), "=r"(ahf[3]) : "r"(a1));
                    asm volatile("ldmatrix.sync.aligned.m8n8.x4.shared.b16 {%0,%1,%2,%3}, [%4];"
                        : "=r"(alf[0]), "=r"(alf[1]), "=r"(alf[2]), "=r"(alf[3]) : "r"(a2));
                } else {
                    int sw = (r >> 1) & 3;
                    uint32_t a1 = sb + r * 64 + ((ckh ^ sw) << 4);
                    asm volatile("ldmatrix.sync.aligned.m8n8.x4.shared.b16 {%0,%1,%2,%3}, [%4];"
                        : "=r"(ahf[0]), "=r"(ahf[1]), "=r"(ahf[2]), "=r"(ahf[3]) : "r"(a1));
                }
#define MMA(A0,A1,A2,A3,B0,B1) \
    asm volatile("mma.sync.aligned.m16n8k16.row.col.f32.f16.f16.f32 " \
        "{%0,%1,%2,%3}, {%4,%5,%6,%7}, {%8,%9}, {%0,%1,%2,%3};" \
        : "+f"(c[mt][nt][0]), "+f"(c[mt][nt][1]), "+f"(c[mt][nt][2]), "+f"(c[mt][nt][3]) \
        : "r"(A0), "r"(A1), "r"(A2), "r"(A3), "r"(B0), "r"(B1))
#pragma unroll
                for (int nt = 0; nt < 4; ++nt) {
                    MMA(ahf[0],ahf[1],ahf[2],ahf[3], bhf[nt][0],bhf[nt][1]);
                }
                if (LO) {
#pragma unroll
                    for (int nt = 0; nt < 4; ++nt) {
                        MMA(alf[0],alf[1],alf[2],alf[3], bhf[nt][0],bhf[nt][1]);
                    }
                }
#undef MMA
            }
        }
        __syncthreads();
    }

    // epilogue
#pragma unroll
    for (int mt = 0; mt < MT; ++mt) {
        int row = m0 + warp_m * (BM / 2) + mt * 16 + (lane >> 2);
#pragma unroll
        for (int nt = 0; nt < 4; ++nt) {
            int col = n0 + warp_n * 32 + nt * 8 + 2 * (lane & 3);
            float b0 = bias[col], b1 = bias[col + 1];
            float v0 = c[mt][nt][0] + b0, v1 = c[mt][nt][1] + b1;
            float v2 = c[mt][nt][2] + b0, v3 = c[mt][nt][3] + b1;
            if (mode == 1) {
                v0 = fmaxf(v0, 0.f); v1 = fmaxf(v1, 0.f);
                v2 = fmaxf(v2, 0.f); v3 = fmaxf(v3, 0.f);
                __half h0,l0,h1,l1,h2,l2,h3,l3;
                split2h(v0,h0,l0); split2h(v1,h1,l1); split2h(v2,h2,l2); split2h(v3,h3,l3);
                *(__half2*)&Ch[(size_t)row * Nn + col] = __halves2half2(h0, h1);
                *(__half2*)&Cl[(size_t)row * Nn + col] = __halves2half2(l0, l1);
                *(__half2*)&Ch[(size_t)(row + 8) * Nn + col] = __halves2half2(h2, h3);
                *(__half2*)&Cl[(size_t)(row + 8) * Nn + col] = __halves2half2(l2, l3);
            } else {
                *(float2*)&Cf[(size_t)row * Nn + col] = make_float2(v0, v1);
                *(float2*)&Cf[(size_t)(row + 8) * Nn + col] = make_float2(v2, v3);
            }
        }
    }
}

// ---------------- per-column std of X (train rows) -> xmul ----------------
__global__ void k_xstats() {
    int c = blockIdx.x * 256 + threadIdx.x;
    float s[8] = {}, ss[8] = {};
    for (int n = 0; n < CN; n += 8) {
#pragma unroll
        for (int u = 0; u < 8; ++u) {
            float v = g_X[(size_t)(n + u) * CNH + c];
            s[u] += v; ss[u] += v * v;
        }
    }
    double S = 0.0, SS = 0.0;
#pragma unroll
    for (int u = 0; u < 8; ++u) { S += (double)s[u]; SS += (double)ss[u]; }
    double var = (SS - S * S / (double)CN) / (double)(CN - 1);
    if (var < 0.0) var = 0.0;
    g_xmul[c] = (float)sqrt(var) + 0.1f;
}

// ---------------- Gram partials (xmul folded) ----------------
__global__ __launch_bounds__(256) void k_cov() {
    int g = blockIdx.x, sp = blockIdx.y, tid = threadIdx.x;
    __shared__ float tile[32][68];
    __shared__ float xminv[64];
    if (tid < 64) xminv[tid] = 1.0f / g_xmul[g * 64 + tid];
    __syncthreads();
    const int ti = (tid & 15) * 4, tj = (tid >> 4) * 4;
    float acc[4][4] = {};
    for (int n0 = sp * 512; n0 < sp * 512 + 512; n0 += 32) {
#pragma unroll
        for (int it = 0; it < 2; ++it) {
            int idx = tid + it * 256;
            int r = idx >> 4, c4 = idx & 15;
            float4 v = *(const float4*)&g_X[(size_t)(n0 + r) * CNH + g * 64 + c4 * 4];
            v.x *= xminv[c4*4+0]; v.y *= xminv[c4*4+1];
            v.z *= xminv[c4*4+2]; v.w *= xminv[c4*4+3];
            *(float4*)&tile[r][c4 * 4] = v;
        }
        __syncthreads();
#pragma unroll 4
        for (int r = 0; r < 32; ++r) {
            float xi[4], xj[4];
            *(float4*)xi = *(const float4*)&tile[r][ti];
            *(float4*)xj = *(const float4*)&tile[r][tj];
#pragma unroll
            for (int a = 0; a < 4; ++a)
#pragma unroll
                for (int b = 0; b < 4; ++b)
                    acc[a][b] = fmaf(xi[a], xj[b], acc[a][b]);
        }
        __syncthreads();
    }
    float* out = &g_Mpart[sp][g * 4096];
#pragma unroll
    for (int a = 0; a < 4; ++a)
#pragma unroll
        for (int b = 0; b < 4; ++b)
            out[(ti + a) * 64 + (tj + b)] = acc[a][b];
}

// ---------------- a partials (xmul folded) ----------------
__global__ __launch_bounds__(256) void k_apart() {
    int c = blockIdx.x * 256 + threadIdx.x;
    int sp = blockIdx.y;
    int n0 = sp * 256;
    __shared__ float ys[256 * CNY];
    for (int i = threadIdx.x; i < 256 * CNY; i += 256) ys[i] = g_Yc[n0 * CNY + i];
    __syncthreads();
    float xinv = 1.0f / g_xmul[c];
    float acc[CNY] = {};
    for (int n = 0; n < 256; ++n) {
        float v = g_X[(size_t)(n0 + n) * CNH + c] * xinv;
#pragma unroll
        for (int j = 0; j < CNY; ++j) acc[j] = fmaf(v, ys[n * CNY + j], acc[j]);
    }
#pragma unroll
    for (int j = 0; j < CNY; ++j) g_apart[sp][c * CNY + j] = acc[j];
}

// ---------------- Cholesky + logdet + inverse ----------------
__global__ __launch_bounds__(64) void k_chol() {
    int g = blockIdx.x, tid = threadIdx.x;
    __shared__ float A[64][65];
    __shared__ float Yv[64][64];
    float rg = g_scal[0], t = g_scal[1];
    for (int i = 0; i < 64; ++i) {
        float m = 0.f;
#pragma unroll
        for (int sp = 0; sp < 4; ++sp) m += g_Mpart[sp][g * 4096 + i * 64 + tid];
        A[i][tid] = t * m + (i == tid ? rg : 0.f);
    }
    __syncthreads();
    for (int k = 0; k < 64; ++k) {
        float akk = A[k][k];
        float skk = sqrtf(akk);
        __syncthreads();
        if (tid == k) A[k][k] = skk;
        else if (tid > k) A[tid][k] = A[tid][k] / skk;
        __syncthreads();
        if (tid > k) {
            float lik = A[tid][k];
            for (int j = k + 1; j <= tid; ++j) A[tid][j] -= lik * A[j][k];
        }
        __syncthreads();
    }
    if (tid == 0) {
        float s = 0.f;
        for (int i = 0; i < 64; ++i) s += logf(A[i][i]);
        g_S[g] = 2.f * s;
    }
    const int c = tid;
    for (int i = 0; i < 64; ++i) {
        if (i < c) { Yv[i][c] = 0.f; continue; }
        float s = (i == c) ? 1.f : 0.f;
        for (int j = c; j < i; ++j) s -= A[i][j] * Yv[j][c];
        Yv[i][c] = s / A[i][i];
    }
    for (int i = 63; i >= 0; --i) {
        float s = Yv[i][c];
        for (int j = i + 1; j < 64; ++j) s -= A[j][i] * Yv[j][c];
        Yv[i][c] = s / A[i][i];
    }
    __syncthreads();
    for (int i = 0; i < 64; ++i) g_cov[g * 4096 + i * 64 + c] = Yv[i][c];
}

// ---------------- w0, cw ----------------
__global__ __launch_bounds__(256) void k_w0cw() {
    int g = blockIdx.x, tid = threadIdx.x;
    __shared__ float covs[64][65];
    __shared__ float as[64][17];
    __shared__ float w0s[64][17];
    for (int idx = tid; idx < 4096; idx += 256)
        covs[idx >> 6][idx & 63] = g_cov[g * 4096 + idx];
    for (int idx = tid; idx < 64 * CNY; idx += 256) {
        int i = idx >> 4, j = idx & 15;
        float s = 0.f;
#pragma unroll
        for (int sp = 0; sp < 8; ++sp) s += g_apart[sp][(g * 64 + i) * CNY + j];
        as[i][j] = s;
    }
    __syncthreads();
    float t = g_scal[1];
    int j = tid & 15, i0 = (tid >> 4) * 4;
#pragma unroll
    for (int ii = 0; ii < 4; ++ii) {
        float s = 0.f;
        for (int k = 0; k < 64; ++k) s = fmaf(covs[i0 + ii][k], as[k][j], s);
        w0s[i0 + ii][j] = t * s;
    }
    __syncthreads();
#pragma unroll
    for (int ii = 0; ii < 4; ++ii) {
        float s = 0.f;
        for (int k = 0; k < 64; ++k) s = fmaf(covs[i0 + ii][k], w0s[k][j], s);
        g_cw[(g * 64 + i0 + ii) * CNY + j] = s;
        g_w0[(g * 64 + i0 + ii) * CNY + j] = w0s[i0 + ii][j];
    }
}

// ---------------- softmax over groups ----------------
__global__ __launch_bounds__(1024) void k_p() {
    int tid = threadIdx.x;
    int g = tid >> 4, j = tid & 15;
    float corr = 0.f;
    for (int i = 0; i < 64; ++i)
        corr = fmaf(g_w0[(g * 64 + i) * CNY + j], g_cw[(g * 64 + i) * CNY + j], corr);
    float t = g_scal[1];
    float lg = corr - t * g_ycss[j] - g_S[g];
    __shared__ float L[64][17];
    __shared__ float mx[16], sm[16];
    L[g][j] = lg;
    __syncthreads();
    if (tid < 16) {
        float m = -1e30f;
        for (int gg = 0; gg < 64; ++gg) m = fmaxf(m, L[gg][tid]);
        float s = 0.f;
        for (int gg = 0; gg < 64; ++gg) s += expf(L[gg][tid] - m);
        mx[tid] = m; sm[tid] = s;
    }
    __syncthreads();
    g_p[g * CNY + j] = expf(lg - mx[j]) / sm[j];
}

// ---------------- fold xmul into w and cov (merged) ----------------
__global__ void k_fold() {
    int idx = blockIdx.x * 256 + threadIdx.x;
    if (idx < CNH * CNY) {
        int c = idx >> 4, j = idx & 15;
        g_w[idx] = g_w0[idx] * g_p[(c >> 6) * CNY + j] / g_xmul[c];
    }
    int g = idx >> 12, i = (idx >> 6) & 63, j = idx & 63;
    g_covv[idx] = g_cov[idx] / (g_xmul[g * 64 + i] * g_xmul[g * 64 + j]);
}

// ---------------- predict partials: groups split PSPLIT ways ----------------
__global__ __launch_bounds__(128) void k_predict_part(const float* __restrict__ XQ) {
    const int tid = threadIdx.x;
    const int r = tid >> 3, lane = tid & 7;
    const int row0 = blockIdx.x * 16;
    const int g0 = blockIdx.y * (CG / PSPLIT);
    __shared__ float Xs[16][65];
    __shared__ float Cs[64][65];
    __shared__ float Ws[64][17];
    __shared__ float ps[16];
    float accy[CNY] = {};
    float v0 = 0.f, v1 = 0.f;
    for (int g = g0; g < g0 + CG / PSPLIT; ++g) {
#pragma unroll
        for (int it = 0; it < 8; ++it) {
            int idx = tid + it * 128;
            Xs[idx >> 6][idx & 63] = XQ[(size_t)(row0 + (idx >> 6)) * CNH + g * 64 + (idx & 63)];
        }
#pragma unroll
        for (int it = 0; it < 32; ++it) {
            int idx = tid + it * 128;
            Cs[idx >> 6][idx & 63] = g_covv[g * 4096 + idx];
        }
#pragma unroll
        for (int it = 0; it < 8; ++it) {
            int idx = tid + it * 128;
            Ws[idx >> 4][idx & 15] = g_w[(g * 64 + (idx >> 4)) * CNY + (idx & 15)];
        }
        if (tid < 16) ps[tid] = g_p[g * CNY + tid];
        __syncthreads();
        float x[8];
#pragma unroll
        for (int ii = 0; ii < 8; ++ii) x[ii] = Xs[r][lane * 8 + ii];
#pragma unroll
        for (int ii = 0; ii < 8; ++ii)
#pragma unroll
            for (int j = 0; j < CNY; ++j)
                accy[j] = fmaf(x[ii], Ws[lane * 8 + ii][j], accy[j]);
        float s = 0.f;
        for (int jc = 0; jc < 64; ++jc) {
            float xj = Xs[r][jc];
            float q = 0.f;
#pragma unroll
            for (int ii = 0; ii < 8; ++ii) q = fmaf(Cs[lane * 8 + ii][jc], x[ii], q);
            s = fmaf(q, xj, s);
        }
        s += __shfl_xor_sync(0xffffffffu, s, 4);
        s += __shfl_xor_sync(0xffffffffu, s, 2);
        s += __shfl_xor_sync(0xffffffffu, s, 1);
        v0 = fmaf(s, ps[lane * 2 + 0], v0);
        v1 = fmaf(s, ps[lane * 2 + 1], v1);
        __syncthreads();
    }
#pragma unroll
    for (int j = 0; j < CNY; ++j) {
        accy[j] += __shfl_xor_sync(0xffffffffu, accy[j], 4);
        accy[j] += __shfl_xor_sync(0xffffffffu, accy[j], 2);
        accy[j] += __shfl_xor_sync(0xffffffffu, accy[j], 1);
    }
    const int row = row0 + r;
    const int j0 = lane * 2, j1 = j0 + 1;
    g_accp[blockIdx.y][row * CNY + j0] = accy[j0];
    g_accp[blockIdx.y][row * CNY + j1] = accy[j1];
    g_vp[blockIdx.y][row * CNY + j0] = v0;
    g_vp[blockIdx.y][row * CNY + j1] = v1;
}

// ---------------- predict combine ----------------
__global__ void k_predict_comb(float* __restrict__ out) {
    int idx = blockIdx.x * 256 + threadIdx.x;
    int j = idx & 15;
    float a = 0.f, v = 0.f;
#pragma unroll
    for (int s = 0; s < PSPLIT; ++s) { a += g_accp[s][idx]; v += g_vp[s][idx]; }
    out[idx] = (a + g_bmean[j]) * g_ymul[j];
    out[CN * CNY + idx] = sqrtf(fmaxf(v, 0.f)) * g_ymul[j];
}

// ---------------- launcher ----------------
extern "C" void kernel_launch(void* const* d_in, const int* in_sizes, int n_in,
                              void* d_out, int out_size) {
    const void* x  = d_in[0];
    const float* y = (const float*)d_in[1];
    const void* qx = d_in[2];
    const float* we = (const float*)d_in[3];
    const float* W1 = (const float*)d_in[4];
    const float* b1 = (const float*)d_in[5];
    const float* W2 = (const float*)d_in[6];
    const float* b2 = (const float*)d_in[7];
    const float* W3 = (const float*)d_in[8];
    const float* b3 = (const float*)d_in[9];
    const float* rp = (const float*)d_in[10];
    const float* tp = (const float*)d_in[11];
    float* out = (float*)d_out;

    __half *peh, *ph1h, *ph1l, *ph2h, *ph2l;
    __half *pW1h, *pW2h, *pW3h;
    float *pX;
    cudaGetSymbolAddress((void**)&peh,  g_eh);
    cudaGetSymbolAddress((void**)&ph1h, g_h1h);
    cudaGetSymbolAddress((void**)&ph1l, g_h1l);
    cudaGetSymbolAddress((void**)&ph2h, g_h2h);
    cudaGetSymbolAddress((void**)&ph2l, g_h2l);
    cudaGetSymbolAddress((void**)&pW1h, g_W1h);
    cudaGetSymbolAddress((void**)&pW2h, g_W2h);
    cudaGetSymbolAddress((void**)&pW3h, g_W3h);
    cudaGetSymbolAddress((void**)&pX,  g_X);
    float* pXQ = pX + (size_t)CN * CNH;

    const int SM64NL = 2 * (64 * 64 + 8192);     // 24 KB (hi-only A)
    const int SM64   = 2 * (64 * 128 + 8192);    // 32 KB
    const int SM128  = 2 * (128 * 128 + 8192);   // 48 KB
    cudaFuncSetAttribute((void*)k_gemm_fp16<64, false>, cudaFuncAttributeMaxDynamicSharedMemorySize, SM64NL);
    cudaFuncSetAttribute((void*)k_gemm_fp16<64, true>,  cudaFuncAttributeMaxDynamicSharedMemorySize, SM64);
    cudaFuncSetAttribute((void*)k_gemm_fp16<128, true>, cudaFuncAttributeMaxDynamicSharedMemorySize, SM128);

    // launches 1-3, captured launch (#4) is GEMM1
    k_detect<<<1, 256>>>((const int*)x, in_sizes[0]);
    k_wh<<<(NW1 + NW2 + NW3 + 255) / 256, 256>>>((const float4*)W1, (const float4*)W2, (const float4*)W3);
    const int gatherBlocks = (CN2 * (CNIN / 4) + 255) / 256;
    k_gather<<<gatherBlocks, 256>>>(x, qx, (const float4*)we, peh);

    k_gemm_fp16<64, false><<<dim3(CH / 128, CN2 / 64), 256, SM64NL>>>(peh, nullptr, pW1h, b1, nullptr, ph1h, ph1l, CN2, CH, CNIN, 1);
    k_gemm_fp16<64, true><<<dim3(CH / 128, CN2 / 64), 256, SM64>>>(ph1h, ph1l, pW2h, b2, nullptr, ph2h, ph2l, CN2, CH, CH, 1);
    k_gemm_fp16<128, true><<<dim3(CNH / 128, CN2 / 128), 256, SM128>>>(ph2h, ph2l, pW3h, b3, pX, nullptr, nullptr, CN2, CNH, CH, 0);

    // ridge learn
    k_scal<<<1, 1>>>(rp, tp);
    k_ystats<<<16, 256>>>(y);
    k_xstats<<<CNH / 256, 256>>>();
    k_cov<<<dim3(CG, 4), 256>>>();
    k_apart<<<dim3(CNH / 256, 8), 256>>>();
    k_chol<<<CG, 64>>>();
    k_w0cw<<<CG, 256>>>();
    k_p<<<1, 1024>>>();
    k_fold<<<(CG * 64 * 64) / 256, 256>>>();

    // predict: group-split partials + combine
    k_predict_part<<<dim3(CN / 16, PSPLIT), 128>>>(pXQ);
    k_predict_comb<<<(CN * CNY) / 256, 256>>>(out);
}

// round 15
// speedup vs baseline: 1.0567x; 1.0002x over previous
#include <cuda_runtime.h>
#include <cuda_fp16.h>
#include <math.h>
#include <stdint.h>

// ---------------- problem constants ----------------
#define CN   2048
#define CN2  4096
#define CNY  16
#define CL   8
#define CD   768
#define CNIN 6144
#define CH   512
#define CNH  4096
#define CG   64
#define CV   50257
#define PSPLIT 8

// ---------------- device scratch ----------------
__device__ __align__(16) __half g_eh[CN2 * CNIN];
__device__ __align__(16) __half g_h1h[CN2 * CH];
__device__ __align__(16) __half g_h1l[CN2 * CH];
__device__ __align__(16) __half g_h2h[CN2 * CH];
__device__ __align__(16) __half g_h2l[CN2 * CH];
__device__ __align__(16) __half g_W1h[CH * CNIN];
__device__ __align__(16) __half g_W2h[CH * CH];
__device__ __align__(16) __half g_W3h[CNH * CH];
__device__ __align__(16) float g_X [CN2 * CNH];
__device__ __align__(16) float g_xmul[CNH];
__device__ __align__(16) float g_Yc[CN * CNY];
__device__ __align__(16) float g_ymul[CNY];
__device__ __align__(16) float g_bmean[CNY];
__device__ __align__(16) float g_ycss[CNY];
__device__ __align__(16) float g_scal[2];
__device__ __align__(16) float g_Mpart[4][CG * 64 * 64];
__device__ __align__(16) float g_apart[8][CNH * CNY];
__device__ __align__(16) float g_cov [CG * 64 * 64];
__device__ __align__(16) float g_covv[CG * 64 * 64];
__device__ __align__(16) float g_S[CG];
__device__ __align__(16) float g_w0[CNH * CNY];
__device__ __align__(16) float g_cw[CNH * CNY];
__device__ __align__(16) float g_p [CG * CNY];
__device__ __align__(16) float g_w [CNH * CNY];
__device__ __align__(16) float g_accp[PSPLIT][CN * CNY];
__device__ __align__(16) float g_vp  [PSPLIT][CN * CNY];
__device__ int g_tok64;

// ---------------- small kernels ----------------
__global__ void k_detect(const int* __restrict__ t, int n_elems) {
    __shared__ int nz;
    if (threadIdx.x == 0) nz = 0;
    __syncthreads();
    int local = 0;
    for (int i = 2 * threadIdx.x + 1; i < n_elems; i += 2 * 256)
        if (t[i] != 0) local = 1;
    if (local) atomicOr(&nz, 1);
    __syncthreads();
    if (threadIdx.x == 0) g_tok64 = (nz == 0) ? 1 : 0;
}

__global__ void k_scal(const float* __restrict__ rp, const float* __restrict__ tp) {
    g_scal[0] = expf(rp[0]) + 1e-8f;
    g_scal[1] = expf(tp[0]) + 1e-8f;
}

__global__ void k_ystats(const float* __restrict__ y) {
    int j = blockIdx.x, tid = threadIdx.x;
    __shared__ float red[256];
    __shared__ float sh_ym, sh_b;
    float s = 0.f, ss = 0.f;
    for (int n = tid; n < CN; n += 256) { float v = y[n * CNY + j]; s += v; ss += v * v; }
    red[tid] = s; __syncthreads();
    for (int st = 128; st; st >>= 1) { if (tid < st) red[tid] += red[tid + st]; __syncthreads(); }
    float S = red[0]; __syncthreads();
    red[tid] = ss; __syncthreads();
    for (int st = 128; st; st >>= 1) { if (tid < st) red[tid] += red[tid + st]; __syncthreads(); }
    float SS = red[0]; __syncthreads();
    if (tid == 0) {
        float var = (SS - S * S / (float)CN) / (float)(CN - 1);
        float ym = sqrtf(fmaxf(var, 0.f)) + 0.1f;
        float b = (S / (float)CN) / ym;
        sh_ym = ym; sh_b = b;
        g_ymul[j] = ym; g_bmean[j] = b;
    }
    __syncthreads();
    float ym = sh_ym, b = sh_b;
    float cs = 0.f;
    for (int n = tid; n < CN; n += 256) {
        float v = y[n * CNY + j] / ym - b;
        g_Yc[n * CNY + j] = v;
        cs += v * v;
    }
    red[tid] = cs; __syncthreads();
    for (int st = 128; st; st >>= 1) { if (tid < st) red[tid] += red[tid + st]; __syncthreads(); }
    if (tid == 0) g_ycss[j] = red[0];
}

// ---------------- fp16 split helper ----------------
__device__ __forceinline__ void split2h(float x, __half& h, __half& l) {
    h = __float2half_rn(x);
    l = __float2half_rn(x - __half2float(h));
}

// weight convert (hi only)
#define NW1 (CH * CNIN / 4)
#define NW2 (CH * CH / 4)
#define NW3 (CNH * CH / 4)
__global__ void k_wh(const float4* __restrict__ W1, const float4* __restrict__ W2,
                     const float4* __restrict__ W3) {
    int idx = blockIdx.x * 256 + threadIdx.x;
    const float4* src; __half* dh; int li;
    if (idx < NW1)            { src = W1; dh = g_W1h; li = idx; }
    else if (idx < NW1 + NW2) { src = W2; dh = g_W2h; li = idx - NW1; }
    else if (idx < NW1 + NW2 + NW3) { src = W3; dh = g_W3h; li = idx - NW1 - NW2; }
    else return;
    float4 v = src[li];
    ((__half2*)dh)[li*2+0] = __halves2half2(__float2half_rn(v.x), __float2half_rn(v.y));
    ((__half2*)dh)[li*2+1] = __halves2half2(__float2half_rn(v.z), __float2half_rn(v.w));
}

// merged gather -> fp16 hi only
__global__ void k_gather(const void* __restrict__ tokx, const void* __restrict__ tokq,
                         const float4* __restrict__ we4, __half* __restrict__ eh) {
    int idx = blockIdx.x * 256 + threadIdx.x;
    if (idx >= CN2 * (CNIN / 4)) return;
    int r = idx / (CNIN / 4), k4 = idx - r * (CNIN / 4);
    int l = k4 / (CD / 4), c4 = k4 - l * (CD / 4);
    const void* tok = (r < CN) ? tokx : tokq;
    int rr = (r < CN) ? r : r - CN;
    long long t;
    if (g_tok64) t = ((const long long*)tok)[rr * CL + l];
    else         t = (long long)((const int*)tok)[rr * CL + l];
    if (t < 0) t = 0;
    if (t >= CV) t = CV - 1;
    float4 v = we4[(size_t)t * (CD / 4) + c4];
    ((__half2*)eh)[idx*2+0] = __halves2half2(__float2half_rn(v.x), __float2half_rn(v.y));
    ((__half2*)eh)[idx*2+1] = __halves2half2(__float2half_rn(v.z), __float2half_rn(v.w));
}

// ---------------- asymmetric split-fp16 tensor-core GEMM ----------------
// C = A@B^T. LO=true: D += Ah*Bh + Al*Bh. LO=false: D = Ah*Bh only.
// Block BMx128, BK=32, 256 thr, warp grid 2m x 4n, warp tile (BM/2)x32.
// 2-stage cp.async ring, occ 2 CTA/SM. B fragments loaded 2-at-a-time
// with ldmatrix.x4 (tiles: nt k0, nt k1, nt+1 k0, nt+1 k1).
template<int BM, bool LO>
__global__ __launch_bounds__(256, 2) void k_gemm_fp16(
    const __half* __restrict__ Ah, const __half* __restrict__ Al,
    const __half* __restrict__ Bh,
    const float* __restrict__ bias,
    float* __restrict__ Cf, __half* __restrict__ Ch, __half* __restrict__ Cl,
    int M, int Nn, int K, int mode)
{
    constexpr int MT    = BM / 32;
    constexpr int AROWB = LO ? 128 : 64;
    constexpr int ABYT  = BM * AROWB;
    constexpr int STG   = ABYT + 8192;
    constexpr int ACH   = BM * (AROWB / 16);
    constexpr int TCH   = ACH + 512;
    constexpr int ITER  = (TCH + 255) / 256;
    extern __shared__ __align__(16) char smem[];
    const uint32_t sbase = (uint32_t)__cvta_generic_to_shared(smem);
    const int tid = threadIdx.x;
    const int lane = tid & 31, wid = tid >> 5;
    const int warp_m = wid >> 2, warp_n = wid & 3;
    const int m0 = blockIdx.y * BM, n0 = blockIdx.x * 128;
    const int KT = K >> 5;

    float c[MT][4][4];
#pragma unroll
    for (int i = 0; i < MT; ++i)
#pragma unroll
        for (int j = 0; j < 4; ++j)
#pragma unroll
            for (int r = 0; r < 4; ++r) c[i][j][r] = 0.f;

    auto load_tile = [&](int kt, int stage) {
        int k0 = kt << 5;
        uint32_t sb = sbase + stage * STG;
#pragma unroll
        for (int i = 0; i < ITER; ++i) {
            int id = tid + (i << 8);
            if (id >= TCH) break;
            const __half* g;
            uint32_t sa;
            if (id < ACH) {
                if (LO) {
                    int r = id >> 3, ck = id & 7;
                    const __half* src = (ck < 4) ? Ah : Al;
                    g = src + (size_t)(m0 + r) * K + k0 + (ck & 3) * 8;
                    sa = sb + r * 128 + ((ck ^ (r & 7)) << 4);
                } else {
                    int r = id >> 2, ck = id & 3;
                    g = Ah + (size_t)(m0 + r) * K + k0 + ck * 8;
                    sa = sb + r * 64 + ((ck ^ ((r >> 1) & 3)) << 4);
                }
            } else {
                int j = id - ACH;
                int r = j >> 2, ck = j & 3;
                g = Bh + (size_t)(n0 + r) * K + k0 + ck * 8;
                sa = sb + ABYT + r * 64 + ((ck ^ ((r >> 1) & 3)) << 4);
            }
            asm volatile("cp.async.cg.shared.global [%0], [%1], 16;\n" :: "r"(sa), "l"(g));
        }
        asm volatile("cp.async.commit_group;\n");
    };

    if (KT > 0) load_tile(0, 0);

    for (int kt = 0; kt < KT; ++kt) {
        if (kt + 1 < KT) {
            load_tile(kt + 1, (kt + 1) & 1);
            asm volatile("cp.async.wait_group 1;\n");
        } else {
            asm volatile("cp.async.wait_group 0;\n");
        }
        __syncthreads();
        uint32_t sb = sbase + (kt & 1) * STG;

#pragma unroll
        for (int s16 = 0; s16 < 2; ++s16) {
            uint32_t bhf[4][2];
            // B: two ldmatrix.x4, each serving two nt fragments.
            // lane tile t = lane>>3: nt = 2*ntp + (t>>1), ck = 2*s16 + (t&1)
#pragma unroll
            for (int ntp = 0; ntp < 2; ++ntp) {
                int t = lane >> 3;
                int nt = 2 * ntp + (t >> 1);
                int ck = 2 * s16 + (t & 1);
                int r = warp_n * 32 + nt * 8 + (lane & 7);
                uint32_t ba = sb + ABYT + r * 64 + ((ck ^ ((r >> 1) & 3)) << 4);
                asm volatile("ldmatrix.sync.aligned.m8n8.x4.shared.b16 {%0,%1,%2,%3}, [%4];"
                    : "=r"(bhf[2*ntp][0]), "=r"(bhf[2*ntp][1]),
                      "=r"(bhf[2*ntp+1][0]), "=r"(bhf[2*ntp+1][1]) : "r"(ba));
            }
#pragma unroll
            for (int mt = 0; mt < MT; ++mt) {
                int r = warp_m * (BM / 2) + mt * 16 + (lane & 15);
                int ckh = 2 * s16 + (lane >> 4);
                uint32_t ahf[4], alf[4];
                if (LO) {
                    int sw = r & 7;
                    uint32_t a1 = sb + r * 128 + ((ckh ^ sw) << 4);
                    uint32_t a2 = sb + r * 128 + (((ckh + 4) ^ sw) << 4);
                    asm volatile("ldmatrix.sync.aligned.m8n8.x4.shared.b16 {%0,%1,%2,%3}, [%4];"
                        : "=r"(ahf[0]), "=r"(ahf[1]), "=r"(ahf[2]), "=r"(ahf[3]) : "r"(a1));
                    asm volatile("ldmatrix.sync.aligned.m8n8.x4.shared.b16 {%0,%1,%2,%3}, [%4];"
                        : "=r"(alf[0]), "=r"(alf[1]), "=r"(alf[2]), "=r"(alf[3]) : "r"(a2));
                } else {
                    int sw = (r >> 1) & 3;
                    uint32_t a1 = sb + r * 64 + ((ckh ^ sw) << 4);
                    asm volatile("ldmatrix.sync.aligned.m8n8.x4.shared.b16 {%0,%1,%2,%3}, [%4];"
                        : "=r"(ahf[0]), "=r"(ahf[1]), "=r"(ahf[2]), "=r"(ahf[3]) : "r"(a1));
                }
#define MMA(A0,A1,A2,A3,B0,B1) \
    asm volatile("mma.sync.aligned.m16n8k16.row.col.f32.f16.f16.f32 " \
        "{%0,%1,%2,%3}, {%4,%5,%6,%7}, {%8,%9}, {%0,%1,%2,%3};" \
        : "+f"(c[mt][nt][0]), "+f"(c[mt][nt][1]), "+f"(c[mt][nt][2]), "+f"(c[mt][nt][3]) \
        : "r"(A0), "r"(A1), "r"(A2), "r"(A3), "r"(B0), "r"(B1))
#pragma unroll
                for (int nt = 0; nt < 4; ++nt) {
                    MMA(ahf[0],ahf[1],ahf[2],ahf[3], bhf[nt][0],bhf[nt][1]);
                }
                if (LO) {
#pragma unroll
                    for (int nt = 0; nt < 4; ++nt) {
                        MMA(alf[0],alf[1],alf[2],alf[3], bhf[nt][0],bhf[nt][1]);
                    }
                }
#undef MMA
            }
        }
        __syncthreads();
    }

    // epilogue
#pragma unroll
    for (int mt = 0; mt < MT; ++mt) {
        int row = m0 + warp_m * (BM / 2) + mt * 16 + (lane >> 2);
#pragma unroll
        for (int nt = 0; nt < 4; ++nt) {
            int col = n0 + warp_n * 32 + nt * 8 + 2 * (lane & 3);
            float b0 = bias[col], b1 = bias[col + 1];
            float v0 = c[mt][nt][0] + b0, v1 = c[mt][nt][1] + b1;
            float v2 = c[mt][nt][2] + b0, v3 = c[mt][nt][3] + b1;
            if (mode == 1) {
                v0 = fmaxf(v0, 0.f); v1 = fmaxf(v1, 0.f);
                v2 = fmaxf(v2, 0.f); v3 = fmaxf(v3, 0.f);
                __half h0,l0,h1,l1,h2,l2,h3,l3;
                split2h(v0,h0,l0); split2h(v1,h1,l1); split2h(v2,h2,l2); split2h(v3,h3,l3);
                *(__half2*)&Ch[(size_t)row * Nn + col] = __halves2half2(h0, h1);
                *(__half2*)&Cl[(size_t)row * Nn + col] = __halves2half2(l0, l1);
                *(__half2*)&Ch[(size_t)(row + 8) * Nn + col] = __halves2half2(h2, h3);
                *(__half2*)&Cl[(size_t)(row + 8) * Nn + col] = __halves2half2(l2, l3);
            } else {
                *(float2*)&Cf[(size_t)row * Nn + col] = make_float2(v0, v1);
                *(float2*)&Cf[(size_t)(row + 8) * Nn + col] = make_float2(v2, v3);
            }
        }
    }
}

// ---------------- per-column std of X (train rows) -> xmul ----------------
__global__ void k_xstats() {
    int c = blockIdx.x * 256 + threadIdx.x;
    float s[8] = {}, ss[8] = {};
    for (int n = 0; n < CN; n += 8) {
#pragma unroll
        for (int u = 0; u < 8; ++u) {
            float v = g_X[(size_t)(n + u) * CNH + c];
            s[u] += v; ss[u] += v * v;
        }
    }
    double S = 0.0, SS = 0.0;
#pragma unroll
    for (int u = 0; u < 8; ++u) { S += (double)s[u]; SS += (double)ss[u]; }
    double var = (SS - S * S / (double)CN) / (double)(CN - 1);
    if (var < 0.0) var = 0.0;
    g_xmul[c] = (float)sqrt(var) + 0.1f;
}

// ---------------- Gram partials (xmul folded) ----------------
__global__ __launch_bounds__(256) void k_cov() {
    int g = blockIdx.x, sp = blockIdx.y, tid = threadIdx.x;
    __shared__ float tile[32][68];
    __shared__ float xminv[64];
    if (tid < 64) xminv[tid] = 1.0f / g_xmul[g * 64 + tid];
    __syncthreads();
    const int ti = (tid & 15) * 4, tj = (tid >> 4) * 4;
    float acc[4][4] = {};
    for (int n0 = sp * 512; n0 < sp * 512 + 512; n0 += 32) {
#pragma unroll
        for (int it = 0; it < 2; ++it) {
            int idx = tid + it * 256;
            int r = idx >> 4, c4 = idx & 15;
            float4 v = *(const float4*)&g_X[(size_t)(n0 + r) * CNH + g * 64 + c4 * 4];
            v.x *= xminv[c4*4+0]; v.y *= xminv[c4*4+1];
            v.z *= xminv[c4*4+2]; v.w *= xminv[c4*4+3];
            *(float4*)&tile[r][c4 * 4] = v;
        }
        __syncthreads();
#pragma unroll 4
        for (int r = 0; r < 32; ++r) {
            float xi[4], xj[4];
            *(float4*)xi = *(const float4*)&tile[r][ti];
            *(float4*)xj = *(const float4*)&tile[r][tj];
#pragma unroll
            for (int a = 0; a < 4; ++a)
#pragma unroll
                for (int b = 0; b < 4; ++b)
                    acc[a][b] = fmaf(xi[a], xj[b], acc[a][b]);
        }
        __syncthreads();
    }
    float* out = &g_Mpart[sp][g * 4096];
#pragma unroll
    for (int a = 0; a < 4; ++a)
#pragma unroll
        for (int b = 0; b < 4; ++b)
            out[(ti + a) * 64 + (tj + b)] = acc[a][b];
}

// ---------------- a partials (xmul folded) ----------------
__global__ __launch_bounds__(256) void k_apart() {
    int c = blockIdx.x * 256 + threadIdx.x;
    int sp = blockIdx.y;
    int n0 = sp * 256;
    __shared__ float ys[256 * CNY];
    for (int i = threadIdx.x; i < 256 * CNY; i += 256) ys[i] = g_Yc[n0 * CNY + i];
    __syncthreads();
    float xinv = 1.0f / g_xmul[c];
    float acc[CNY] = {};
    for (int n = 0; n < 256; ++n) {
        float v = g_X[(size_t)(n0 + n) * CNH + c] * xinv;
#pragma unroll
        for (int j = 0; j < CNY; ++j) acc[j] = fmaf(v, ys[n * CNY + j], acc[j]);
    }
#pragma unroll
    for (int j = 0; j < CNY; ++j) g_apart[sp][c * CNY + j] = acc[j];
}

// ---------------- Cholesky + logdet + inverse ----------------
__global__ __launch_bounds__(64) void k_chol() {
    int g = blockIdx.x, tid = threadIdx.x;
    __shared__ float A[64][65];
    __shared__ float Yv[64][64];
    float rg = g_scal[0], t = g_scal[1];
    for (int i = 0; i < 64; ++i) {
        float m = 0.f;
#pragma unroll
        for (int sp = 0; sp < 4; ++sp) m += g_Mpart[sp][g * 4096 + i * 64 + tid];
        A[i][tid] = t * m + (i == tid ? rg : 0.f);
    }
    __syncthreads();
    for (int k = 0; k < 64; ++k) {
        float akk = A[k][k];
        float skk = sqrtf(akk);
        __syncthreads();
        if (tid == k) A[k][k] = skk;
        else if (tid > k) A[tid][k] = A[tid][k] / skk;
        __syncthreads();
        if (tid > k) {
            float lik = A[tid][k];
            for (int j = k + 1; j <= tid; ++j) A[tid][j] -= lik * A[j][k];
        }
        __syncthreads();
    }
    if (tid == 0) {
        float s = 0.f;
        for (int i = 0; i < 64; ++i) s += logf(A[i][i]);
        g_S[g] = 2.f * s;
    }
    const int c = tid;
    for (int i = 0; i < 64; ++i) {
        if (i < c) { Yv[i][c] = 0.f; continue; }
        float s = (i == c) ? 1.f : 0.f;
        for (int j = c; j < i; ++j) s -= A[i][j] * Yv[j][c];
        Yv[i][c] = s / A[i][i];
    }
    for (int i = 63; i >= 0; --i) {
        float s = Yv[i][c];
        for (int j = i + 1; j < 64; ++j) s -= A[j][i] * Yv[j][c];
        Yv[i][c] = s / A[i][i];
    }
    __syncthreads();
    for (int i = 0; i < 64; ++i) g_cov[g * 4096 + i * 64 + c] = Yv[i][c];
}

// ---------------- w0, cw ----------------
__global__ __launch_bounds__(256) void k_w0cw() {
    int g = blockIdx.x, tid = threadIdx.x;
    __shared__ float covs[64][65];
    __shared__ float as[64][17];
    __shared__ float w0s[64][17];
    for (int idx = tid; idx < 4096; idx += 256)
        covs[idx >> 6][idx & 63] = g_cov[g * 4096 + idx];
    for (int idx = tid; idx < 64 * CNY; idx += 256) {
        int i = idx >> 4, j = idx & 15;
        float s = 0.f;
#pragma unroll
        for (int sp = 0; sp < 8; ++sp) s += g_apart[sp][(g * 64 + i) * CNY + j];
        as[i][j] = s;
    }
    __syncthreads();
    float t = g_scal[1];
    int j = tid & 15, i0 = (tid >> 4) * 4;
#pragma unroll
    for (int ii = 0; ii < 4; ++ii) {
        float s = 0.f;
        for (int k = 0; k < 64; ++k) s = fmaf(covs[i0 + ii][k], as[k][j], s);
        w0s[i0 + ii][j] = t * s;
    }
    __syncthreads();
#pragma unroll
    for (int ii = 0; ii < 4; ++ii) {
        float s = 0.f;
        for (int k = 0; k < 64; ++k) s = fmaf(covs[i0 + ii][k], w0s[k][j], s);
        g_cw[(g * 64 + i0 + ii) * CNY + j] = s;
        g_w0[(g * 64 + i0 + ii) * CNY + j] = w0s[i0 + ii][j];
    }
}

// ---------------- softmax over groups ----------------
__global__ __launch_bounds__(1024) void k_p() {
    int tid = threadIdx.x;
    int g = tid >> 4, j = tid & 15;
    float corr = 0.f;
    for (int i = 0; i < 64; ++i)
        corr = fmaf(g_w0[(g * 64 + i) * CNY + j], g_cw[(g * 64 + i) * CNY + j], corr);
    float t = g_scal[1];
    float lg = corr - t * g_ycss[j] - g_S[g];
    __shared__ float L[64][17];
    __shared__ float mx[16], sm[16];
    L[g][j] = lg;
    __syncthreads();
    if (tid < 16) {
        float m = -1e30f;
        for (int gg = 0; gg < 64; ++gg) m = fmaxf(m, L[gg][tid]);
        float s = 0.f;
        for (int gg = 0; gg < 64; ++gg) s += expf(L[gg][tid] - m);
        mx[tid] = m; sm[tid] = s;
    }
    __syncthreads();
    g_p[g * CNY + j] = expf(lg - mx[j]) / sm[j];
}

// ---------------- fold xmul into w and cov (merged) ----------------
__global__ void k_fold() {
    int idx = blockIdx.x * 256 + threadIdx.x;
    if (idx < CNH * CNY) {
        int c = idx >> 4, j = idx & 15;
        g_w[idx] = g_w0[idx] * g_p[(c >> 6) * CNY + j] / g_xmul[c];
    }
    int g = idx >> 12, i = (idx >> 6) & 63, j = idx & 63;
    g_covv[idx] = g_cov[idx] / (g_xmul[g * 64 + i] * g_xmul[g * 64 + j]);
}

// ---------------- predict partials: groups split PSPLIT ways ----------------
__global__ __launch_bounds__(128) void k_predict_part(const float* __restrict__ XQ) {
    const int tid = threadIdx.x;
    const int r = tid >> 3, lane = tid & 7;
    const int row0 = blockIdx.x * 16;
    const int g0 = blockIdx.y * (CG / PSPLIT);
    __shared__ float Xs[16][65];
    __shared__ float Cs[64][65];
    __shared__ float Ws[64][17];
    __shared__ float ps[16];
    float accy[CNY] = {};
    float v0 = 0.f, v1 = 0.f;
    for (int g = g0; g < g0 + CG / PSPLIT; ++g) {
#pragma unroll
        for (int it = 0; it < 8; ++it) {
            int idx = tid + it * 128;
            Xs[idx >> 6][idx & 63] = XQ[(size_t)(row0 + (idx >> 6)) * CNH + g * 64 + (idx & 63)];
        }
#pragma unroll
        for (int it = 0; it < 32; ++it) {
            int idx = tid + it * 128;
            Cs[idx >> 6][idx & 63] = g_covv[g * 4096 + idx];
        }
#pragma unroll
        for (int it = 0; it < 8; ++it) {
            int idx = tid + it * 128;
            Ws[idx >> 4][idx & 15] = g_w[(g * 64 + (idx >> 4)) * CNY + (idx & 15)];
        }
        if (tid < 16) ps[tid] = g_p[g * CNY + tid];
        __syncthreads();
        float x[8];
#pragma unroll
        for (int ii = 0; ii < 8; ++ii) x[ii] = Xs[r][lane * 8 + ii];
#pragma unroll
        for (int ii = 0; ii < 8; ++ii)
#pragma unroll
            for (int j = 0; j < CNY; ++j)
                accy[j] = fmaf(x[ii], Ws[lane * 8 + ii][j], accy[j]);
        float s = 0.f;
        for (int jc = 0; jc < 64; ++jc) {
            float xj = Xs[r][jc];
            float q = 0.f;
#pragma unroll
            for (int ii = 0; ii < 8; ++ii) q = fmaf(Cs[lane * 8 + ii][jc], x[ii], q);
            s = fmaf(q, xj, s);
        }
        s += __shfl_xor_sync(0xffffffffu, s, 4);
        s += __shfl_xor_sync(0xffffffffu, s, 2);
        s += __shfl_xor_sync(0xffffffffu, s, 1);
        v0 = fmaf(s, ps[lane * 2 + 0], v0);
        v1 = fmaf(s, ps[lane * 2 + 1], v1);
        __syncthreads();
    }
#pragma unroll
    for (int j = 0; j < CNY; ++j) {
        accy[j] += __shfl_xor_sync(0xffffffffu, accy[j], 4);
        accy[j] += __shfl_xor_sync(0xffffffffu, accy[j], 2);
        accy[j] += __shfl_xor_sync(0xffffffffu, accy[j], 1);
    }
    const int row = row0 + r;
    const int j0 = lane * 2, j1 = j0 + 1;
    g_accp[blockIdx.y][row * CNY + j0] = accy[j0];
    g_accp[blockIdx.y][row * CNY + j1] = accy[j1];
    g_vp[blockIdx.y][row * CNY + j0] = v0;
    g_vp[blockIdx.y][row * CNY + j1] = v1;
}

// ---------------- predict combine ----------------
__global__ void k_predict_comb(float* __restrict__ out) {
    int idx = blockIdx.x * 256 + threadIdx.x;
    int j = idx & 15;
    float a = 0.f, v = 0.f;
#pragma unroll
    for (int s = 0; s < PSPLIT; ++s) { a += g_accp[s][idx]; v += g_vp[s][idx]; }
    out[idx] = (a + g_bmean[j]) * g_ymul[j];
    out[CN * CNY + idx] = sqrtf(fmaxf(v, 0.f)) * g_ymul[j];
}

// ---------------- launcher ----------------
extern "C" void kernel_launch(void* const* d_in, const int* in_sizes, int n_in,
                              void* d_out, int out_size) {
    const void* x  = d_in[0];
    const float* y = (const float*)d_in[1];
    const void* qx = d_in[2];
    const float* we = (const float*)d_in[3];
    const float* W1 = (const float*)d_in[4];
    const float* b1 = (const float*)d_in[5];
    const float* W2 = (const float*)d_in[6];
    const float* b2 = (const float*)d_in[7];
    const float* W3 = (const float*)d_in[8];
    const float* b3 = (const float*)d_in[9];
    const float* rp = (const float*)d_in[10];
    const float* tp = (const float*)d_in[11];
    float* out = (float*)d_out;

    __half *peh, *ph1h, *ph1l, *ph2h, *ph2l;
    __half *pW1h, *pW2h, *pW3h;
    float *pX;
    cudaGetSymbolAddress((void**)&peh,  g_eh);
    cudaGetSymbolAddress((void**)&ph1h, g_h1h);
    cudaGetSymbolAddress((void**)&ph1l, g_h1l);
    cudaGetSymbolAddress((void**)&ph2h, g_h2h);
    cudaGetSymbolAddress((void**)&ph2l, g_h2l);
    cudaGetSymbolAddress((void**)&pW1h, g_W1h);
    cudaGetSymbolAddress((void**)&pW2h, g_W2h);
    cudaGetSymbolAddress((void**)&pW3h, g_W3h);
    cudaGetSymbolAddress((void**)&pX,  g_X);
    float* pXQ = pX + (size_t)CN * CNH;

    const int SM64NL = 2 * (64 * 64 + 8192);     // 24 KB (hi-only A)
    const int SM64   = 2 * (64 * 128 + 8192);    // 32 KB
    const int SM128  = 2 * (128 * 128 + 8192);   // 48 KB
    cudaFuncSetAttribute((void*)k_gemm_fp16<64, false>, cudaFuncAttributeMaxDynamicSharedMemorySize, SM64NL);
    cudaFuncSetAttribute((void*)k_gemm_fp16<64, true>,  cudaFuncAttributeMaxDynamicSharedMemorySize, SM64);
    cudaFuncSetAttribute((void*)k_gemm_fp16<128, true>, cudaFuncAttributeMaxDynamicSharedMemorySize, SM128);

    // launches 1-3, captured launch (#4) is GEMM1
    k_detect<<<1, 256>>>((const int*)x, in_sizes[0]);
    k_wh<<<(NW1 + NW2 + NW3 + 255) / 256, 256>>>((const float4*)W1, (const float4*)W2, (const float4*)W3);
    const int gatherBlocks = (CN2 * (CNIN / 4) + 255) / 256;
    k_gather<<<gatherBlocks, 256>>>(x, qx, (const float4*)we, peh);

    k_gemm_fp16<64, false><<<dim3(CH / 128, CN2 / 64), 256, SM64NL>>>(peh, nullptr, pW1h, b1, nullptr, ph1h, ph1l, CN2, CH, CNIN, 1);
    k_gemm_fp16<64, true><<<dim3(CH / 128, CN2 / 64), 256, SM64>>>(ph1h, ph1l, pW2h, b2, nullptr, ph2h, ph2l, CN2, CH, CH, 1);
    k_gemm_fp16<128, true><<<dim3(CNH / 128, CN2 / 128), 256, SM128>>>(ph2h, ph2l, pW3h, b3, pX, nullptr, nullptr, CN2, CNH, CH, 0);

    // ridge learn
    k_scal<<<1, 1>>>(rp, tp);
    k_ystats<<<16, 256>>>(y);
    k_xstats<<<CNH / 256, 256>>>();
    k_cov<<<dim3(CG, 4), 256>>>();
    k_apart<<<dim3(CNH / 256, 8), 256>>>();
    k_chol<<<CG, 64>>>();
    k_w0cw<<<CG, 256>>>();
    k_p<<<1, 1024>>>();
    k_fold<<<(CG * 64 * 64) / 256, 256>>>();

    // predict: group-split partials + combine
    k_predict_part<<<dim3(CN / 16, PSPLIT), 128>>>(pXQ);
    k_predict_comb<<<(CN * CNY) / 256, 256>>>(out);
}

// round 16
// speedup vs baseline: 1.0616x; 1.0046x over previous
#include <cuda_runtime.h>
#include <cuda_fp16.h>
#include <math.h>
#include <stdint.h>

// ---------------- problem constants ----------------
#define CN   2048
#define CN2  4096
#define CNY  16
#define CL   8
#define CD   768
#define CNIN 6144
#define CH   512
#define CNH  4096
#define CG   64
#define CV   50257
#define PSPLIT 16

// ---------------- device scratch ----------------
__device__ __align__(16) __half g_eh[CN2 * CNIN];
__device__ __align__(16) __half g_h1h[CN2 * CH];
__device__ __align__(16) __half g_h1l[CN2 * CH];
__device__ __align__(16) __half g_h2h[CN2 * CH];
__device__ __align__(16) __half g_h2l[CN2 * CH];
__device__ __align__(16) __half g_W1h[CH * CNIN];
__device__ __align__(16) __half g_W2h[CH * CH];
__device__ __align__(16) __half g_W3h[CNH * CH];
__device__ __align__(16) float g_X [CN2 * CNH];
__device__ __align__(16) float g_xmul[CNH];
__device__ __align__(16) float g_Yc[CN * CNY];
__device__ __align__(16) float g_ymul[CNY];
__device__ __align__(16) float g_bmean[CNY];
__device__ __align__(16) float g_ycss[CNY];
__device__ __align__(16) float g_scal[2];
__device__ __align__(16) float g_Mpart[4][CG * 64 * 64];
__device__ __align__(16) float g_apart[8][CNH * CNY];
__device__ __align__(16) float g_cov [CG * 64 * 64];
__device__ __align__(16) float g_covv[CG * 64 * 64];
__device__ __align__(16) float g_S[CG];
__device__ __align__(16) float g_w0[CNH * CNY];
__device__ __align__(16) float g_cw[CNH * CNY];
__device__ __align__(16) float g_p [CG * CNY];
__device__ __align__(16) float g_w [CNH * CNY];
__device__ __align__(16) float g_accp[PSPLIT][CN * CNY];
__device__ __align__(16) float g_vp  [PSPLIT][CN * CNY];
__device__ int g_tok64;

// ---------------- small kernels ----------------
__global__ void k_detect(const int* __restrict__ t, int n_elems) {
    __shared__ int nz;
    if (threadIdx.x == 0) nz = 0;
    __syncthreads();
    int local = 0;
    for (int i = 2 * threadIdx.x + 1; i < n_elems; i += 2 * 256)
        if (t[i] != 0) local = 1;
    if (local) atomicOr(&nz, 1);
    __syncthreads();
    if (threadIdx.x == 0) g_tok64 = (nz == 0) ? 1 : 0;
}

__global__ void k_scal(const float* __restrict__ rp, const float* __restrict__ tp) {
    g_scal[0] = expf(rp[0]) + 1e-8f;
    g_scal[1] = expf(tp[0]) + 1e-8f;
}

__global__ void k_ystats(const float* __restrict__ y) {
    int j = blockIdx.x, tid = threadIdx.x;
    __shared__ float red[256];
    __shared__ float sh_ym, sh_b;
    float s = 0.f, ss = 0.f;
    for (int n = tid; n < CN; n += 256) { float v = y[n * CNY + j]; s += v; ss += v * v; }
    red[tid] = s; __syncthreads();
    for (int st = 128; st; st >>= 1) { if (tid < st) red[tid] += red[tid + st]; __syncthreads(); }
    float S = red[0]; __syncthreads();
    red[tid] = ss; __syncthreads();
    for (int st = 128; st; st >>= 1) { if (tid < st) red[tid] += red[tid + st]; __syncthreads(); }
    float SS = red[0]; __syncthreads();
    if (tid == 0) {
        float var = (SS - S * S / (float)CN) / (float)(CN - 1);
        float ym = sqrtf(fmaxf(var, 0.f)) + 0.1f;
        float b = (S / (float)CN) / ym;
        sh_ym = ym; sh_b = b;
        g_ymul[j] = ym; g_bmean[j] = b;
    }
    __syncthreads();
    float ym = sh_ym, b = sh_b;
    float cs = 0.f;
    for (int n = tid; n < CN; n += 256) {
        float v = y[n * CNY + j] / ym - b;
        g_Yc[n * CNY + j] = v;
        cs += v * v;
    }
    red[tid] = cs; __syncthreads();
    for (int st = 128; st; st >>= 1) { if (tid < st) red[tid] += red[tid + st]; __syncthreads(); }
    if (tid == 0) g_ycss[j] = red[0];
}

// ---------------- fp16 split helper ----------------
__device__ __forceinline__ void split2h(float x, __half& h, __half& l) {
    h = __float2half_rn(x);
    l = __float2half_rn(x - __half2float(h));
}

// weight convert (hi only)
#define NW1 (CH * CNIN / 4)
#define NW2 (CH * CH / 4)
#define NW3 (CNH * CH / 4)
__global__ void k_wh(const float4* __restrict__ W1, const float4* __restrict__ W2,
                     const float4* __restrict__ W3) {
    int idx = blockIdx.x * 256 + threadIdx.x;
    const float4* src; __half* dh; int li;
    if (idx < NW1)            { src = W1; dh = g_W1h; li = idx; }
    else if (idx < NW1 + NW2) { src = W2; dh = g_W2h; li = idx - NW1; }
    else if (idx < NW1 + NW2 + NW3) { src = W3; dh = g_W3h; li = idx - NW1 - NW2; }
    else return;
    float4 v = src[li];
    ((__half2*)dh)[li*2+0] = __halves2half2(__float2half_rn(v.x), __float2half_rn(v.y));
    ((__half2*)dh)[li*2+1] = __halves2half2(__float2half_rn(v.z), __float2half_rn(v.w));
}

// merged gather -> fp16 hi only
__global__ void k_gather(const void* __restrict__ tokx, const void* __restrict__ tokq,
                         const float4* __restrict__ we4, __half* __restrict__ eh) {
    int idx = blockIdx.x * 256 + threadIdx.x;
    if (idx >= CN2 * (CNIN / 4)) return;
    int r = idx / (CNIN / 4), k4 = idx - r * (CNIN / 4);
    int l = k4 / (CD / 4), c4 = k4 - l * (CD / 4);
    const void* tok = (r < CN) ? tokx : tokq;
    int rr = (r < CN) ? r : r - CN;
    long long t;
    if (g_tok64) t = ((const long long*)tok)[rr * CL + l];
    else         t = (long long)((const int*)tok)[rr * CL + l];
    if (t < 0) t = 0;
    if (t >= CV) t = CV - 1;
    float4 v = we4[(size_t)t * (CD / 4) + c4];
    ((__half2*)eh)[idx*2+0] = __halves2half2(__float2half_rn(v.x), __float2half_rn(v.y));
    ((__half2*)eh)[idx*2+1] = __halves2half2(__float2half_rn(v.z), __float2half_rn(v.w));
}

// ---------------- asymmetric split-fp16 tensor-core GEMM ----------------
// C = A@B^T. LO=true: D += Ah*Bh + Al*Bh. LO=false: D = Ah*Bh only.
// Block BMx128, BK=32, 256 thr, warp grid 2m x 4n, warp tile (BM/2)x32.
// 2-stage cp.async ring, occ NB CTA/SM (NB=3 for the light LO=false variant).
template<int BM, bool LO, int NB>
__global__ __launch_bounds__(256, NB) void k_gemm_fp16(
    const __half* __restrict__ Ah, const __half* __restrict__ Al,
    const __half* __restrict__ Bh,
    const float* __restrict__ bias,
    float* __restrict__ Cf, __half* __restrict__ Ch, __half* __restrict__ Cl,
    int M, int Nn, int K, int mode)
{
    constexpr int MT    = BM / 32;
    constexpr int AROWB = LO ? 128 : 64;
    constexpr int ABYT  = BM * AROWB;
    constexpr int STG   = ABYT + 8192;
    constexpr int ACH   = BM * (AROWB / 16);
    constexpr int TCH   = ACH + 512;
    constexpr int ITER  = (TCH + 255) / 256;
    extern __shared__ __align__(16) char smem[];
    const uint32_t sbase = (uint32_t)__cvta_generic_to_shared(smem);
    const int tid = threadIdx.x;
    const int lane = tid & 31, wid = tid >> 5;
    const int warp_m = wid >> 2, warp_n = wid & 3;
    const int m0 = blockIdx.y * BM, n0 = blockIdx.x * 128;
    const int KT = K >> 5;

    float c[MT][4][4];
#pragma unroll
    for (int i = 0; i < MT; ++i)
#pragma unroll
        for (int j = 0; j < 4; ++j)
#pragma unroll
            for (int r = 0; r < 4; ++r) c[i][j][r] = 0.f;

    auto load_tile = [&](int kt, int stage) {
        int k0 = kt << 5;
        uint32_t sb = sbase + stage * STG;
#pragma unroll
        for (int i = 0; i < ITER; ++i) {
            int id = tid + (i << 8);
            if (id >= TCH) break;
            const __half* g;
            uint32_t sa;
            if (id < ACH) {
                if (LO) {
                    int r = id >> 3, ck = id & 7;
                    const __half* src = (ck < 4) ? Ah : Al;
                    g = src + (size_t)(m0 + r) * K + k0 + (ck & 3) * 8;
                    sa = sb + r * 128 + ((ck ^ (r & 7)) << 4);
                } else {
                    int r = id >> 2, ck = id & 3;
                    g = Ah + (size_t)(m0 + r) * K + k0 + ck * 8;
                    sa = sb + r * 64 + ((ck ^ ((r >> 1) & 3)) << 4);
                }
            } else {
                int j = id - ACH;
                int r = j >> 2, ck = j & 3;
                g = Bh + (size_t)(n0 + r) * K + k0 + ck * 8;
                sa = sb + ABYT + r * 64 + ((ck ^ ((r >> 1) & 3)) << 4);
            }
            asm volatile("cp.async.cg.shared.global [%0], [%1], 16;\n" :: "r"(sa), "l"(g));
        }
        asm volatile("cp.async.commit_group;\n");
    };

    if (KT > 0) load_tile(0, 0);

    for (int kt = 0; kt < KT; ++kt) {
        if (kt + 1 < KT) {
            load_tile(kt + 1, (kt + 1) & 1);
            asm volatile("cp.async.wait_group 1;\n");
        } else {
            asm volatile("cp.async.wait_group 0;\n");
        }
        __syncthreads();
        uint32_t sb = sbase + (kt & 1) * STG;

#pragma unroll
        for (int s16 = 0; s16 < 2; ++s16) {
            uint32_t bhf[4][2];
#pragma unroll
            for (int nt = 0; nt < 4; ++nt) {
                int r = warp_n * 32 + nt * 8 + (lane & 7);
                int ck = 2 * s16 + ((lane >> 3) & 1);
                uint32_t b1 = sb + ABYT + r * 64 + ((ck ^ ((r >> 1) & 3)) << 4);
                asm volatile("ldmatrix.sync.aligned.m8n8.x2.shared.b16 {%0,%1}, [%2];"
                    : "=r"(bhf[nt][0]), "=r"(bhf[nt][1]) : "r"(b1));
            }
#pragma unroll
            for (int mt = 0; mt < MT; ++mt) {
                int r = warp_m * (BM / 2) + mt * 16 + (lane & 15);
                int ckh = 2 * s16 + (lane >> 4);
                uint32_t ahf[4], alf[4];
                if (LO) {
                    int sw = r & 7;
                    uint32_t a1 = sb + r * 128 + ((ckh ^ sw) << 4);
                    uint32_t a2 = sb + r * 128 + (((ckh + 4) ^ sw) << 4);
                    asm volatile("ldmatrix.sync.aligned.m8n8.x4.shared.b16 {%0,%1,%2,%3}, [%4];"
                        : "=r"(ahf[0]), "=r"(ahf[1]), "=r"(ahf[2]), "=r"(ahf[3]) : "r"(a1));
                    asm volatile("ldmatrix.sync.aligned.m8n8.x4.shared.b16 {%0,%1,%2,%3}, [%4];"
                        : "=r"(alf[0]), "=r"(alf[1]), "=r"(alf[2]), "=r"(alf[3]) : "r"(a2));
                } else {
                    int sw = (r >> 1) & 3;
                    uint32_t a1 = sb + r * 64 + ((ckh ^ sw) << 4);
                    asm volatile("ldmatrix.sync.aligned.m8n8.x4.shared.b16 {%0,%1,%2,%3}, [%4];"
                        : "=r"(ahf[0]), "=r"(ahf[1]), "=r"(ahf[2]), "=r"(ahf[3]) : "r"(a1));
                }
#define MMA(A0,A1,A2,A3,B0,B1) \
    asm volatile("mma.sync.aligned.m16n8k16.row.col.f32.f16.f16.f32 " \
        "{%0,%1,%2,%3}, {%4,%5,%6,%7}, {%8,%9}, {%0,%1,%2,%3};" \
        : "+f"(c[mt][nt][0]), "+f"(c[mt][nt][1]), "+f"(c[mt][nt][2]), "+f"(c[mt][nt][3]) \
        : "r"(A0), "r"(A1), "r"(A2), "r"(A3), "r"(B0), "r"(B1))
#pragma unroll
                for (int nt = 0; nt < 4; ++nt) {
                    MMA(ahf[0],ahf[1],ahf[2],ahf[3], bhf[nt][0],bhf[nt][1]);
                }
                if (LO) {
#pragma unroll
                    for (int nt = 0; nt < 4; ++nt) {
                        MMA(alf[0],alf[1],alf[2],alf[3], bhf[nt][0],bhf[nt][1]);
                    }
                }
#undef MMA
            }
        }
        __syncthreads();
    }

    // epilogue
#pragma unroll
    for (int mt = 0; mt < MT; ++mt) {
        int row = m0 + warp_m * (BM / 2) + mt * 16 + (lane >> 2);
#pragma unroll
        for (int nt = 0; nt < 4; ++nt) {
            int col = n0 + warp_n * 32 + nt * 8 + 2 * (lane & 3);
            float b0 = bias[col], b1 = bias[col + 1];
            float v0 = c[mt][nt][0] + b0, v1 = c[mt][nt][1] + b1;
            float v2 = c[mt][nt][2] + b0, v3 = c[mt][nt][3] + b1;
            if (mode == 1) {
                v0 = fmaxf(v0, 0.f); v1 = fmaxf(v1, 0.f);
                v2 = fmaxf(v2, 0.f); v3 = fmaxf(v3, 0.f);
                __half h0,l0,h1,l1,h2,l2,h3,l3;
                split2h(v0,h0,l0); split2h(v1,h1,l1); split2h(v2,h2,l2); split2h(v3,h3,l3);
                *(__half2*)&Ch[(size_t)row * Nn + col] = __halves2half2(h0, h1);
                *(__half2*)&Cl[(size_t)row * Nn + col] = __halves2half2(l0, l1);
                *(__half2*)&Ch[(size_t)(row + 8) * Nn + col] = __halves2half2(h2, h3);
                *(__half2*)&Cl[(size_t)(row + 8) * Nn + col] = __halves2half2(l2, l3);
            } else {
                *(float2*)&Cf[(size_t)row * Nn + col] = make_float2(v0, v1);
                *(float2*)&Cf[(size_t)(row + 8) * Nn + col] = make_float2(v2, v3);
            }
        }
    }
}

// ---------------- per-column std of X (train rows) -> xmul ----------------
__global__ void k_xstats() {
    int c = blockIdx.x * 256 + threadIdx.x;
    float s[8] = {}, ss[8] = {};
    for (int n = 0; n < CN; n += 8) {
#pragma unroll
        for (int u = 0; u < 8; ++u) {
            float v = g_X[(size_t)(n + u) * CNH + c];
            s[u] += v; ss[u] += v * v;
        }
    }
    double S = 0.0, SS = 0.0;
#pragma unroll
    for (int u = 0; u < 8; ++u) { S += (double)s[u]; SS += (double)ss[u]; }
    double var = (SS - S * S / (double)CN) / (double)(CN - 1);
    if (var < 0.0) var = 0.0;
    g_xmul[c] = (float)sqrt(var) + 0.1f;
}

// ---------------- Gram partials (xmul folded) ----------------
__global__ __launch_bounds__(256) void k_cov() {
    int g = blockIdx.x, sp = blockIdx.y, tid = threadIdx.x;
    __shared__ float tile[32][68];
    __shared__ float xminv[64];
    if (tid < 64) xminv[tid] = 1.0f / g_xmul[g * 64 + tid];
    __syncthreads();
    const int ti = (tid & 15) * 4, tj = (tid >> 4) * 4;
    float acc[4][4] = {};
    for (int n0 = sp * 512; n0 < sp * 512 + 512; n0 += 32) {
#pragma unroll
        for (int it = 0; it < 2; ++it) {
            int idx = tid + it * 256;
            int r = idx >> 4, c4 = idx & 15;
            float4 v = *(const float4*)&g_X[(size_t)(n0 + r) * CNH + g * 64 + c4 * 4];
            v.x *= xminv[c4*4+0]; v.y *= xminv[c4*4+1];
            v.z *= xminv[c4*4+2]; v.w *= xminv[c4*4+3];
            *(float4*)&tile[r][c4 * 4] = v;
        }
        __syncthreads();
#pragma unroll 4
        for (int r = 0; r < 32; ++r) {
            float xi[4], xj[4];
            *(float4*)xi = *(const float4*)&tile[r][ti];
            *(float4*)xj = *(const float4*)&tile[r][tj];
#pragma unroll
            for (int a = 0; a < 4; ++a)
#pragma unroll
                for (int b = 0; b < 4; ++b)
                    acc[a][b] = fmaf(xi[a], xj[b], acc[a][b]);
        }
        __syncthreads();
    }
    float* out = &g_Mpart[sp][g * 4096];
#pragma unroll
    for (int a = 0; a < 4; ++a)
#pragma unroll
        for (int b = 0; b < 4; ++b)
            out[(ti + a) * 64 + (tj + b)] = acc[a][b];
}

// ---------------- a partials (xmul folded) ----------------
__global__ __launch_bounds__(256) void k_apart() {
    int c = blockIdx.x * 256 + threadIdx.x;
    int sp = blockIdx.y;
    int n0 = sp * 256;
    __shared__ float ys[256 * CNY];
    for (int i = threadIdx.x; i < 256 * CNY; i += 256) ys[i] = g_Yc[n0 * CNY + i];
    __syncthreads();
    float xinv = 1.0f / g_xmul[c];
    float acc[CNY] = {};
    for (int n = 0; n < 256; ++n) {
        float v = g_X[(size_t)(n0 + n) * CNH + c] * xinv;
#pragma unroll
        for (int j = 0; j < CNY; ++j) acc[j] = fmaf(v, ys[n * CNY + j], acc[j]);
    }
#pragma unroll
    for (int j = 0; j < CNY; ++j) g_apart[sp][c * CNY + j] = acc[j];
}

// ---------------- Cholesky + logdet + inverse ----------------
__global__ __launch_bounds__(64) void k_chol() {
    int g = blockIdx.x, tid = threadIdx.x;
    __shared__ float A[64][65];
    __shared__ float Yv[64][64];
    float rg = g_scal[0], t = g_scal[1];
    for (int i = 0; i < 64; ++i) {
        float m = 0.f;
#pragma unroll
        for (int sp = 0; sp < 4; ++sp) m += g_Mpart[sp][g * 4096 + i * 64 + tid];
        A[i][tid] = t * m + (i == tid ? rg : 0.f);
    }
    __syncthreads();
    for (int k = 0; k < 64; ++k) {
        float akk = A[k][k];
        float skk = sqrtf(akk);
        __syncthreads();
        if (tid == k) A[k][k] = skk;
        else if (tid > k) A[tid][k] = A[tid][k] / skk;
        __syncthreads();
        if (tid > k) {
            float lik = A[tid][k];
            for (int j = k + 1; j <= tid; ++j) A[tid][j] -= lik * A[j][k];
        }
        __syncthreads();
    }
    if (tid == 0) {
        float s = 0.f;
        for (int i = 0; i < 64; ++i) s += logf(A[i][i]);
        g_S[g] = 2.f * s;
    }
    const int c = tid;
    for (int i = 0; i < 64; ++i) {
        if (i < c) { Yv[i][c] = 0.f; continue; }
        float s = (i == c) ? 1.f : 0.f;
        for (int j = c; j < i; ++j) s -= A[i][j] * Yv[j][c];
        Yv[i][c] = s / A[i][i];
    }
    for (int i = 63; i >= 0; --i) {
        float s = Yv[i][c];
        for (int j = i + 1; j < 64; ++j) s -= A[j][i] * Yv[j][c];
        Yv[i][c] = s / A[i][i];
    }
    __syncthreads();
    for (int i = 0; i < 64; ++i) g_cov[g * 4096 + i * 64 + c] = Yv[i][c];
}

// ---------------- w0, cw ----------------
__global__ __launch_bounds__(256) void k_w0cw() {
    int g = blockIdx.x, tid = threadIdx.x;
    __shared__ float covs[64][65];
    __shared__ float as[64][17];
    __shared__ float w0s[64][17];
    for (int idx = tid; idx < 4096; idx += 256)
        covs[idx >> 6][idx & 63] = g_cov[g * 4096 + idx];
    for (int idx = tid; idx < 64 * CNY; idx += 256) {
        int i = idx >> 4, j = idx & 15;
        float s = 0.f;
#pragma unroll
        for (int sp = 0; sp < 8; ++sp) s += g_apart[sp][(g * 64 + i) * CNY + j];
        as[i][j] = s;
    }
    __syncthreads();
    float t = g_scal[1];
    int j = tid & 15, i0 = (tid >> 4) * 4;
#pragma unroll
    for (int ii = 0; ii < 4; ++ii) {
        float s = 0.f;
        for (int k = 0; k < 64; ++k) s = fmaf(covs[i0 + ii][k], as[k][j], s);
        w0s[i0 + ii][j] = t * s;
    }
    __syncthreads();
#pragma unroll
    for (int ii = 0; ii < 4; ++ii) {
        float s = 0.f;
        for (int k = 0; k < 64; ++k) s = fmaf(covs[i0 + ii][k], w0s[k][j], s);
        g_cw[(g * 64 + i0 + ii) * CNY + j] = s;
        g_w0[(g * 64 + i0 + ii) * CNY + j] = w0s[i0 + ii][j];
    }
}

// ---------------- softmax over groups ----------------
__global__ __launch_bounds__(1024) void k_p() {
    int tid = threadIdx.x;
    int g = tid >> 4, j = tid & 15;
    float corr = 0.f;
    for (int i = 0; i < 64; ++i)
        corr = fmaf(g_w0[(g * 64 + i) * CNY + j], g_cw[(g * 64 + i) * CNY + j], corr);
    float t = g_scal[1];
    float lg = corr - t * g_ycss[j] - g_S[g];
    __shared__ float L[64][17];
    __shared__ float mx[16], sm[16];
    L[g][j] = lg;
    __syncthreads();
    if (tid < 16) {
        float m = -1e30f;
        for (int gg = 0; gg < 64; ++gg) m = fmaxf(m, L[gg][tid]);
        float s = 0.f;
        for (int gg = 0; gg < 64; ++gg) s += expf(L[gg][tid] - m);
        mx[tid] = m; sm[tid] = s;
    }
    __syncthreads();
    g_p[g * CNY + j] = expf(lg - mx[j]) / sm[j];
}

// ---------------- fold xmul into w and cov (merged) ----------------
__global__ void k_fold() {
    int idx = blockIdx.x * 256 + threadIdx.x;
    if (idx < CNH * CNY) {
        int c = idx >> 4, j = idx & 15;
        g_w[idx] = g_w0[idx] * g_p[(c >> 6) * CNY + j] / g_xmul[c];
    }
    int g = idx >> 12, i = (idx >> 6) & 63, j = idx & 63;
    g_covv[idx] = g_cov[idx] / (g_xmul[g * 64 + i] * g_xmul[g * 64 + j]);
}

// ---------------- predict partials: groups split PSPLIT ways ----------------
__global__ __launch_bounds__(128) void k_predict_part(const float* __restrict__ XQ) {
    const int tid = threadIdx.x;
    const int r = tid >> 3, lane = tid & 7;
    const int row0 = blockIdx.x * 16;
    const int g0 = blockIdx.y * (CG / PSPLIT);
    __shared__ float Xs[16][65];
    __shared__ float Cs[64][65];
    __shared__ float Ws[64][17];
    __shared__ float ps[16];
    float accy[CNY] = {};
    float v0 = 0.f, v1 = 0.f;
    for (int g = g0; g < g0 + CG / PSPLIT; ++g) {
#pragma unroll
        for (int it = 0; it < 8; ++it) {
            int idx = tid + it * 128;
            Xs[idx >> 6][idx & 63] = XQ[(size_t)(row0 + (idx >> 6)) * CNH + g * 64 + (idx & 63)];
        }
#pragma unroll
        for (int it = 0; it < 32; ++it) {
            int idx = tid + it * 128;
            Cs[idx >> 6][idx & 63] = g_covv[g * 4096 + idx];
        }
#pragma unroll
        for (int it = 0; it < 8; ++it) {
            int idx = tid + it * 128;
            Ws[idx >> 4][idx & 15] = g_w[(g * 64 + (idx >> 4)) * CNY + (idx & 15)];
        }
        if (tid < 16) ps[tid] = g_p[g * CNY + tid];
        __syncthreads();
        float x[8];
#pragma unroll
        for (int ii = 0; ii < 8; ++ii) x[ii] = Xs[r][lane * 8 + ii];
#pragma unroll
        for (int ii = 0; ii < 8; ++ii)
#pragma unroll
            for (int j = 0; j < CNY; ++j)
                accy[j] = fmaf(x[ii], Ws[lane * 8 + ii][j], accy[j]);
        float s = 0.f;
        for (int jc = 0; jc < 64; ++jc) {
            float xj = Xs[r][jc];
            float q = 0.f;
#pragma unroll
            for (int ii = 0; ii < 8; ++ii) q = fmaf(Cs[lane * 8 + ii][jc], x[ii], q);
            s = fmaf(q, xj, s);
        }
        s += __shfl_xor_sync(0xffffffffu, s, 4);
        s += __shfl_xor_sync(0xffffffffu, s, 2);
        s += __shfl_xor_sync(0xffffffffu, s, 1);
        v0 = fmaf(s, ps[lane * 2 + 0], v0);
        v1 = fmaf(s, ps[lane * 2 + 1], v1);
        __syncthreads();
    }
#pragma unroll
    for (int j = 0; j < CNY; ++j) {
        accy[j] += __shfl_xor_sync(0xffffffffu, accy[j], 4);
        accy[j] += __shfl_xor_sync(0xffffffffu, accy[j], 2);
        accy[j] += __shfl_xor_sync(0xffffffffu, accy[j], 1);
    }
    const int row = row0 + r;
    const int j0 = lane * 2, j1 = j0 + 1;
    g_accp[blockIdx.y][row * CNY + j0] = accy[j0];
    g_accp[blockIdx.y][row * CNY + j1] = accy[j1];
    g_vp[blockIdx.y][row * CNY + j0] = v0;
    g_vp[blockIdx.y][row * CNY + j1] = v1;
}

// ---------------- predict combine ----------------
__global__ void k_predict_comb(float* __restrict__ out) {
    int idx = blockIdx.x * 256 + threadIdx.x;
    int j = idx & 15;
    float a = 0.f, v = 0.f;
#pragma unroll
    for (int s = 0; s < PSPLIT; ++s) { a += g_accp[s][idx]; v += g_vp[s][idx]; }
    out[idx] = (a + g_bmean[j]) * g_ymul[j];
    out[CN * CNY + idx] = sqrtf(fmaxf(v, 0.f)) * g_ymul[j];
}

// ---------------- launcher ----------------
extern "C" void kernel_launch(void* const* d_in, const int* in_sizes, int n_in,
                              void* d_out, int out_size) {
    const void* x  = d_in[0];
    const float* y = (const float*)d_in[1];
    const void* qx = d_in[2];
    const float* we = (const float*)d_in[3];
    const float* W1 = (const float*)d_in[4];
    const float* b1 = (const float*)d_in[5];
    const float* W2 = (const float*)d_in[6];
    const float* b2 = (const float*)d_in[7];
    const float* W3 = (const float*)d_in[8];
    const float* b3 = (const float*)d_in[9];
    const float* rp = (const float*)d_in[10];
    const float* tp = (const float*)d_in[11];
    float* out = (float*)d_out;

    __half *peh, *ph1h, *ph1l, *ph2h, *ph2l;
    __half *pW1h, *pW2h, *pW3h;
    float *pX;
    cudaGetSymbolAddress((void**)&peh,  g_eh);
    cudaGetSymbolAddress((void**)&ph1h, g_h1h);
    cudaGetSymbolAddress((void**)&ph1l, g_h1l);
    cudaGetSymbolAddress((void**)&ph2h, g_h2h);
    cudaGetSymbolAddress((void**)&ph2l, g_h2l);
    cudaGetSymbolAddress((void**)&pW1h, g_W1h);
    cudaGetSymbolAddress((void**)&pW2h, g_W2h);
    cudaGetSymbolAddress((void**)&pW3h, g_W3h);
    cudaGetSymbolAddress((void**)&pX,  g_X);
    float* pXQ = pX + (size_t)CN * CNH;

    const int SM64NL = 2 * (64 * 64 + 8192);     // 24 KB (hi-only A)
    const int SM64   = 2 * (64 * 128 + 8192);    // 32 KB
    const int SM128  = 2 * (128 * 128 + 8192);   // 48 KB
    cudaFuncSetAttribute((void*)k_gemm_fp16<64, false, 3>, cudaFuncAttributeMaxDynamicSharedMemorySize, SM64NL);
    cudaFuncSetAttribute((void*)k_gemm_fp16<64, true, 2>,  cudaFuncAttributeMaxDynamicSharedMemorySize, SM64);
    cudaFuncSetAttribute((void*)k_gemm_fp16<128, true, 2>, cudaFuncAttributeMaxDynamicSharedMemorySize, SM128);

    // launches 1-3, captured launch (#4) is GEMM1
    k_detect<<<1, 256>>>((const int*)x, in_sizes[0]);
    k_wh<<<(NW1 + NW2 + NW3 + 255) / 256, 256>>>((const float4*)W1, (const float4*)W2, (const float4*)W3);
    const int gatherBlocks = (CN2 * (CNIN / 4) + 255) / 256;
    k_gather<<<gatherBlocks, 256>>>(x, qx, (const float4*)we, peh);

    k_gemm_fp16<64, false, 3><<<dim3(CH / 128, CN2 / 64), 256, SM64NL>>>(peh, nullptr, pW1h, b1, nullptr, ph1h, ph1l, CN2, CH, CNIN, 1);
    k_gemm_fp16<64, true, 2><<<dim3(CH / 128, CN2 / 64), 256, SM64>>>(ph1h, ph1l, pW2h, b2, nullptr, ph2h, ph2l, CN2, CH, CH, 1);
    k_gemm_fp16<128, true, 2><<<dim3(CNH / 128, CN2 / 128), 256, SM128>>>(ph2h, ph2l, pW3h, b3, pX, nullptr, nullptr, CN2, CNH, CH, 0);

    // ridge learn
    k_scal<<<1, 1>>>(rp, tp);
    k_ystats<<<16, 256>>>(y);
    k_xstats<<<CNH / 256, 256>>>();
    k_cov<<<dim3(CG, 4), 256>>>();
    k_apart<<<dim3(CNH / 256, 8), 256>>>();
    k_chol<<<CG, 64>>>();
    k_w0cw<<<CG, 256>>>();
    k_p<<<1, 1024>>>();
    k_fold<<<(CG * 64 * 64) / 256, 256>>>();

    // predict: group-split partials + combine
    k_predict_part<<<dim3(CN / 16, PSPLIT), 128>>>(pXQ);
    k_predict_comb<<<(CN * CNY) / 256, 256>>>(out);
}

// round 17
// speedup vs baseline: 1.1163x; 1.0516x over previous
#include <cuda_runtime.h>
#include <cuda_fp16.h>
#include <math.h>
#include <stdint.h>

// ---------------- problem constants ----------------
#define CN   2048
#define CN2  4096
#define CNY  16
#define CL   8
#define CD   768
#define CNIN 6144
#define CH   512
#define CNH  4096
#define CG   64
#define CV   50257
#define PSPLIT 16

// ---------------- device scratch ----------------
__device__ __align__(16) __half g_eh[CN2 * CNIN];
__device__ __align__(16) __half g_h1h[CN2 * CH];
__device__ __align__(16) __half g_h1l[CN2 * CH];
__device__ __align__(16) __half g_h2h[CN2 * CH];
__device__ __align__(16) __half g_h2l[CN2 * CH];
__device__ __align__(16) __half g_W1h[CH * CNIN];
__device__ __align__(16) __half g_W2h[CH * CH];
__device__ __align__(16) __half g_W3h[CNH * CH];
__device__ __align__(16) float g_X [CN2 * CNH];
__device__ __align__(16) float g_xmul[CNH];
__device__ __align__(16) float g_Yc[CN * CNY];
__device__ __align__(16) float g_ymul[CNY];
__device__ __align__(16) float g_bmean[CNY];
__device__ __align__(16) float g_ycss[CNY];
__device__ __align__(16) float g_scal[2];
__device__ __align__(16) float g_Mpart[4][CG * 64 * 64];
__device__ __align__(16) float g_apart[8][CNH * CNY];
__device__ __align__(16) float g_cov [CG * 64 * 64];
__device__ __align__(16) float g_covv[CG * 64 * 64];
__device__ __align__(16) float g_S[CG];
__device__ __align__(16) float g_w0[CNH * CNY];
__device__ __align__(16) float g_cw[CNH * CNY];
__device__ __align__(16) float g_p [CG * CNY];
__device__ __align__(16) float g_w [CNH * CNY];
__device__ __align__(16) float g_accp[PSPLIT][CN * CNY];
__device__ __align__(16) float g_vp  [PSPLIT][CN * CNY];
__device__ int g_tok64;

// ---------------- small kernels ----------------
__global__ void k_detect(const int* __restrict__ t, int n_elems) {
    __shared__ int nz;
    if (threadIdx.x == 0) nz = 0;
    __syncthreads();
    int local = 0;
    for (int i = 2 * threadIdx.x + 1; i < n_elems; i += 2 * 256)
        if (t[i] != 0) local = 1;
    if (local) atomicOr(&nz, 1);
    __syncthreads();
    if (threadIdx.x == 0) g_tok64 = (nz == 0) ? 1 : 0;
}

__global__ void k_scal(const float* __restrict__ rp, const float* __restrict__ tp) {
    g_scal[0] = expf(rp[0]) + 1e-8f;
    g_scal[1] = expf(tp[0]) + 1e-8f;
}

__global__ void k_ystats(const float* __restrict__ y) {
    int j = blockIdx.x, tid = threadIdx.x;
    __shared__ float red[256];
    __shared__ float sh_ym, sh_b;
    float s = 0.f, ss = 0.f;
    for (int n = tid; n < CN; n += 256) { float v = y[n * CNY + j]; s += v; ss += v * v; }
    red[tid] = s; __syncthreads();
    for (int st = 128; st; st >>= 1) { if (tid < st) red[tid] += red[tid + st]; __syncthreads(); }
    float S = red[0]; __syncthreads();
    red[tid] = ss; __syncthreads();
    for (int st = 128; st; st >>= 1) { if (tid < st) red[tid] += red[tid + st]; __syncthreads(); }
    float SS = red[0]; __syncthreads();
    if (tid == 0) {
        float var = (SS - S * S / (float)CN) / (float)(CN - 1);
        float ym = sqrtf(fmaxf(var, 0.f)) + 0.1f;
        float b = (S / (float)CN) / ym;
        sh_ym = ym; sh_b = b;
        g_ymul[j] = ym; g_bmean[j] = b;
    }
    __syncthreads();
    float ym = sh_ym, b = sh_b;
    float cs = 0.f;
    for (int n = tid; n < CN; n += 256) {
        float v = y[n * CNY + j] / ym - b;
        g_Yc[n * CNY + j] = v;
        cs += v * v;
    }
    red[tid] = cs; __syncthreads();
    for (int st = 128; st; st >>= 1) { if (tid < st) red[tid] += red[tid + st]; __syncthreads(); }
    if (tid == 0) g_ycss[j] = red[0];
}

// ---------------- fp16 split helper ----------------
__device__ __forceinline__ void split2h(float x, __half& h, __half& l) {
    h = __float2half_rn(x);
    l = __float2half_rn(x - __half2float(h));
}

// weight convert (hi only)
#define NW1 (CH * CNIN / 4)
#define NW2 (CH * CH / 4)
#define NW3 (CNH * CH / 4)
__global__ void k_wh(const float4* __restrict__ W1, const float4* __restrict__ W2,
                     const float4* __restrict__ W3) {
    int idx = blockIdx.x * 256 + threadIdx.x;
    const float4* src; __half* dh; int li;
    if (idx < NW1)            { src = W1; dh = g_W1h; li = idx; }
    else if (idx < NW1 + NW2) { src = W2; dh = g_W2h; li = idx - NW1; }
    else if (idx < NW1 + NW2 + NW3) { src = W3; dh = g_W3h; li = idx - NW1 - NW2; }
    else return;
    float4 v = src[li];
    ((__half2*)dh)[li*2+0] = __halves2half2(__float2half_rn(v.x), __float2half_rn(v.y));
    ((__half2*)dh)[li*2+1] = __halves2half2(__float2half_rn(v.z), __float2half_rn(v.w));
}

// merged gather -> fp16 hi only
__global__ void k_gather(const void* __restrict__ tokx, const void* __restrict__ tokq,
                         const float4* __restrict__ we4, __half* __restrict__ eh) {
    int idx = blockIdx.x * 256 + threadIdx.x;
    if (idx >= CN2 * (CNIN / 4)) return;
    int r = idx / (CNIN / 4), k4 = idx - r * (CNIN / 4);
    int l = k4 / (CD / 4), c4 = k4 - l * (CD / 4);
    const void* tok = (r < CN) ? tokx : tokq;
    int rr = (r < CN) ? r : r - CN;
    long long t;
    if (g_tok64) t = ((const long long*)tok)[rr * CL + l];
    else         t = (long long)((const int*)tok)[rr * CL + l];
    if (t < 0) t = 0;
    if (t >= CV) t = CV - 1;
    float4 v = we4[(size_t)t * (CD / 4) + c4];
    ((__half2*)eh)[idx*2+0] = __halves2half2(__float2half_rn(v.x), __float2half_rn(v.y));
    ((__half2*)eh)[idx*2+1] = __halves2half2(__float2half_rn(v.z), __float2half_rn(v.w));
}

// ---------------- asymmetric split-fp16 tensor-core GEMM ----------------
// C = A@B^T. LO=true: D += Ah*Bh + Al*Bh. LO=false: D = Ah*Bh only.
// Block BMx128, BK=32, 256 thr, warp grid 2m x 4n, warp tile (BM/2)x32.
// 2-stage cp.async ring.
template<int BM, bool LO, int NB>
__global__ __launch_bounds__(256, NB) void k_gemm_fp16(
    const __half* __restrict__ Ah, const __half* __restrict__ Al,
    const __half* __restrict__ Bh,
    const float* __restrict__ bias,
    float* __restrict__ Cf, __half* __restrict__ Ch, __half* __restrict__ Cl,
    int M, int Nn, int K, int mode)
{
    constexpr int MT    = BM / 32;
    constexpr int AROWB = LO ? 128 : 64;
    constexpr int ABYT  = BM * AROWB;
    constexpr int STG   = ABYT + 8192;
    constexpr int ACH   = BM * (AROWB / 16);
    constexpr int TCH   = ACH + 512;
    constexpr int ITER  = (TCH + 255) / 256;
    extern __shared__ __align__(16) char smem[];
    const uint32_t sbase = (uint32_t)__cvta_generic_to_shared(smem);
    const int tid = threadIdx.x;
    const int lane = tid & 31, wid = tid >> 5;
    const int warp_m = wid >> 2, warp_n = wid & 3;
    const int m0 = blockIdx.y * BM, n0 = blockIdx.x * 128;
    const int KT = K >> 5;

    float c[MT][4][4];
#pragma unroll
    for (int i = 0; i < MT; ++i)
#pragma unroll
        for (int j = 0; j < 4; ++j)
#pragma unroll
            for (int r = 0; r < 4; ++r) c[i][j][r] = 0.f;

    auto load_tile = [&](int kt, int stage) {
        int k0 = kt << 5;
        uint32_t sb = sbase + stage * STG;
#pragma unroll
        for (int i = 0; i < ITER; ++i) {
            int id = tid + (i << 8);
            if (id >= TCH) break;
            const __half* g;
            uint32_t sa;
            if (id < ACH) {
                if (LO) {
                    int r = id >> 3, ck = id & 7;
                    const __half* src = (ck < 4) ? Ah : Al;
                    g = src + (size_t)(m0 + r) * K + k0 + (ck & 3) * 8;
                    sa = sb + r * 128 + ((ck ^ (r & 7)) << 4);
                } else {
                    int r = id >> 2, ck = id & 3;
                    g = Ah + (size_t)(m0 + r) * K + k0 + ck * 8;
                    sa = sb + r * 64 + ((ck ^ ((r >> 1) & 3)) << 4);
                }
            } else {
                int j = id - ACH;
                int r = j >> 2, ck = j & 3;
                g = Bh + (size_t)(n0 + r) * K + k0 + ck * 8;
                sa = sb + ABYT + r * 64 + ((ck ^ ((r >> 1) & 3)) << 4);
            }
            asm volatile("cp.async.cg.shared.global [%0], [%1], 16;\n" :: "r"(sa), "l"(g));
        }
        asm volatile("cp.async.commit_group;\n");
    };

    if (KT > 0) load_tile(0, 0);

    for (int kt = 0; kt < KT; ++kt) {
        if (kt + 1 < KT) {
            load_tile(kt + 1, (kt + 1) & 1);
            asm volatile("cp.async.wait_group 1;\n");
        } else {
            asm volatile("cp.async.wait_group 0;\n");
        }
        __syncthreads();
        uint32_t sb = sbase + (kt & 1) * STG;

#pragma unroll
        for (int s16 = 0; s16 < 2; ++s16) {
            uint32_t bhf[4][2];
#pragma unroll
            for (int nt = 0; nt < 4; ++nt) {
                int r = warp_n * 32 + nt * 8 + (lane & 7);
                int ck = 2 * s16 + ((lane >> 3) & 1);
                uint32_t b1 = sb + ABYT + r * 64 + ((ck ^ ((r >> 1) & 3)) << 4);
                asm volatile("ldmatrix.sync.aligned.m8n8.x2.shared.b16 {%0,%1}, [%2];"
                    : "=r"(bhf[nt][0]), "=r"(bhf[nt][1]) : "r"(b1));
            }
#pragma unroll
            for (int mt = 0; mt < MT; ++mt) {
                int r = warp_m * (BM / 2) + mt * 16 + (lane & 15);
                int ckh = 2 * s16 + (lane >> 4);
                uint32_t ahf[4], alf[4];
                if (LO) {
                    int sw = r & 7;
                    uint32_t a1 = sb + r * 128 + ((ckh ^ sw) << 4);
                    uint32_t a2 = sb + r * 128 + (((ckh + 4) ^ sw) << 4);
                    asm volatile("ldmatrix.sync.aligned.m8n8.x4.shared.b16 {%0,%1,%2,%3}, [%4];"
                        : "=r"(ahf[0]), "=r"(ahf[1]), "=r"(ahf[2]), "=r"(ahf[3]) : "r"(a1));
                    asm volatile("ldmatrix.sync.aligned.m8n8.x4.shared.b16 {%0,%1,%2,%3}, [%4];"
                        : "=r"(alf[0]), "=r"(alf[1]), "=r"(alf[2]), "=r"(alf[3]) : "r"(a2));
                } else {
                    int sw = (r >> 1) & 3;
                    uint32_t a1 = sb + r * 64 + ((ckh ^ sw) << 4);
                    asm volatile("ldmatrix.sync.aligned.m8n8.x4.shared.b16 {%0,%1,%2,%3}, [%4];"
                        : "=r"(ahf[0]), "=r"(ahf[1]), "=r"(ahf[2]), "=r"(ahf[3]) : "r"(a1));
                }
#define MMA(A0,A1,A2,A3,B0,B1) \
    asm volatile("mma.sync.aligned.m16n8k16.row.col.f32.f16.f16.f32 " \
        "{%0,%1,%2,%3}, {%4,%5,%6,%7}, {%8,%9}, {%0,%1,%2,%3};" \
        : "+f"(c[mt][nt][0]), "+f"(c[mt][nt][1]), "+f"(c[mt][nt][2]), "+f"(c[mt][nt][3]) \
        : "r"(A0), "r"(A1), "r"(A2), "r"(A3), "r"(B0), "r"(B1))
#pragma unroll
                for (int nt = 0; nt < 4; ++nt) {
                    MMA(ahf[0],ahf[1],ahf[2],ahf[3], bhf[nt][0],bhf[nt][1]);
                }
                if (LO) {
#pragma unroll
                    for (int nt = 0; nt < 4; ++nt) {
                        MMA(alf[0],alf[1],alf[2],alf[3], bhf[nt][0],bhf[nt][1]);
                    }
                }
#undef MMA
            }
        }
        __syncthreads();
    }

    // epilogue
#pragma unroll
    for (int mt = 0; mt < MT; ++mt) {
        int row = m0 + warp_m * (BM / 2) + mt * 16 + (lane >> 2);
#pragma unroll
        for (int nt = 0; nt < 4; ++nt) {
            int col = n0 + warp_n * 32 + nt * 8 + 2 * (lane & 3);
            float b0 = bias[col], b1 = bias[col + 1];
            float v0 = c[mt][nt][0] + b0, v1 = c[mt][nt][1] + b1;
            float v2 = c[mt][nt][2] + b0, v3 = c[mt][nt][3] + b1;
            if (mode == 1) {
                v0 = fmaxf(v0, 0.f); v1 = fmaxf(v1, 0.f);
                v2 = fmaxf(v2, 0.f); v3 = fmaxf(v3, 0.f);
                __half h0,l0,h1,l1,h2,l2,h3,l3;
                split2h(v0,h0,l0); split2h(v1,h1,l1); split2h(v2,h2,l2); split2h(v3,h3,l3);
                *(__half2*)&Ch[(size_t)row * Nn + col] = __halves2half2(h0, h1);
                *(__half2*)&Cl[(size_t)row * Nn + col] = __halves2half2(l0, l1);
                *(__half2*)&Ch[(size_t)(row + 8) * Nn + col] = __halves2half2(h2, h3);
                *(__half2*)&Cl[(size_t)(row + 8) * Nn + col] = __halves2half2(l2, l3);
            } else {
                *(float2*)&Cf[(size_t)row * Nn + col] = make_float2(v0, v1);
                *(float2*)&Cf[(size_t)(row + 8) * Nn + col] = make_float2(v2, v3);
            }
        }
    }
}

// ---------------- per-column std of X (train rows) -> xmul ----------------
__global__ void k_xstats() {
    int c = blockIdx.x * 256 + threadIdx.x;
    float s[8] = {}, ss[8] = {};
    for (int n = 0; n < CN; n += 8) {
#pragma unroll
        for (int u = 0; u < 8; ++u) {
            float v = g_X[(size_t)(n + u) * CNH + c];
            s[u] += v; ss[u] += v * v;
        }
    }
    double S = 0.0, SS = 0.0;
#pragma unroll
    for (int u = 0; u < 8; ++u) { S += (double)s[u]; SS += (double)ss[u]; }
    double var = (SS - S * S / (double)CN) / (double)(CN - 1);
    if (var < 0.0) var = 0.0;
    g_xmul[c] = (float)sqrt(var) + 0.1f;
}

// ---------------- Gram partials (xmul folded) ----------------
__global__ __launch_bounds__(256) void k_cov() {
    int g = blockIdx.x, sp = blockIdx.y, tid = threadIdx.x;
    __shared__ float tile[32][68];
    __shared__ float xminv[64];
    if (tid < 64) xminv[tid] = 1.0f / g_xmul[g * 64 + tid];
    __syncthreads();
    const int ti = (tid & 15) * 4, tj = (tid >> 4) * 4;
    float acc[4][4] = {};
    for (int n0 = sp * 512; n0 < sp * 512 + 512; n0 += 32) {
#pragma unroll
        for (int it = 0; it < 2; ++it) {
            int idx = tid + it * 256;
            int r = idx >> 4, c4 = idx & 15;
            float4 v = *(const float4*)&g_X[(size_t)(n0 + r) * CNH + g * 64 + c4 * 4];
            v.x *= xminv[c4*4+0]; v.y *= xminv[c4*4+1];
            v.z *= xminv[c4*4+2]; v.w *= xminv[c4*4+3];
            *(float4*)&tile[r][c4 * 4] = v;
        }
        __syncthreads();
#pragma unroll 4
        for (int r = 0; r < 32; ++r) {
            float xi[4], xj[4];
            *(float4*)xi = *(const float4*)&tile[r][ti];
            *(float4*)xj = *(const float4*)&tile[r][tj];
#pragma unroll
            for (int a = 0; a < 4; ++a)
#pragma unroll
                for (int b = 0; b < 4; ++b)
                    acc[a][b] = fmaf(xi[a], xj[b], acc[a][b]);
        }
        __syncthreads();
    }
    float* out = &g_Mpart[sp][g * 4096];
#pragma unroll
    for (int a = 0; a < 4; ++a)
#pragma unroll
        for (int b = 0; b < 4; ++b)
            out[(ti + a) * 64 + (tj + b)] = acc[a][b];
}

// ---------------- a partials (xmul folded) ----------------
__global__ __launch_bounds__(256) void k_apart() {
    int c = blockIdx.x * 256 + threadIdx.x;
    int sp = blockIdx.y;
    int n0 = sp * 256;
    __shared__ float ys[256 * CNY];
    for (int i = threadIdx.x; i < 256 * CNY; i += 256) ys[i] = g_Yc[n0 * CNY + i];
    __syncthreads();
    float xinv = 1.0f / g_xmul[c];
    float acc[CNY] = {};
    for (int n = 0; n < 256; ++n) {
        float v = g_X[(size_t)(n0 + n) * CNH + c] * xinv;
#pragma unroll
        for (int j = 0; j < CNY; ++j) acc[j] = fmaf(v, ys[n * CNY + j], acc[j]);
    }
#pragma unroll
    for (int j = 0; j < CNY; ++j) g_apart[sp][c * CNY + j] = acc[j];
}

// ---------------- Cholesky + logdet + inverse ----------------
__global__ __launch_bounds__(64) void k_chol() {
    int g = blockIdx.x, tid = threadIdx.x;
    __shared__ float A[64][65];
    __shared__ float Yv[64][64];
    float rg = g_scal[0], t = g_scal[1];
    for (int i = 0; i < 64; ++i) {
        float m = 0.f;
#pragma unroll
        for (int sp = 0; sp < 4; ++sp) m += g_Mpart[sp][g * 4096 + i * 64 + tid];
        A[i][tid] = t * m + (i == tid ? rg : 0.f);
    }
    __syncthreads();
    for (int k = 0; k < 64; ++k) {
        float akk = A[k][k];
        float skk = sqrtf(akk);
        __syncthreads();
        if (tid == k) A[k][k] = skk;
        else if (tid > k) A[tid][k] = A[tid][k] / skk;
        __syncthreads();
        if (tid > k) {
            float lik = A[tid][k];
            for (int j = k + 1; j <= tid; ++j) A[tid][j] -= lik * A[j][k];
        }
        __syncthreads();
    }
    if (tid == 0) {
        float s = 0.f;
        for (int i = 0; i < 64; ++i) s += logf(A[i][i]);
        g_S[g] = 2.f * s;
    }
    const int c = tid;
    for (int i = 0; i < 64; ++i) {
        if (i < c) { Yv[i][c] = 0.f; continue; }
        float s = (i == c) ? 1.f : 0.f;
        for (int j = c; j < i; ++j) s -= A[i][j] * Yv[j][c];
        Yv[i][c] = s / A[i][i];
    }
    for (int i = 63; i >= 0; --i) {
        float s = Yv[i][c];
        for (int j = i + 1; j < 64; ++j) s -= A[j][i] * Yv[j][c];
        Yv[i][c] = s / A[i][i];
    }
    __syncthreads();
    for (int i = 0; i < 64; ++i) g_cov[g * 4096 + i * 64 + c] = Yv[i][c];
}

// ---------------- w0, cw ----------------
__global__ __launch_bounds__(256) void k_w0cw() {
    int g = blockIdx.x, tid = threadIdx.x;
    __shared__ float covs[64][65];
    __shared__ float as[64][17];
    __shared__ float w0s[64][17];
    for (int idx = tid; idx < 4096; idx += 256)
        covs[idx >> 6][idx & 63] = g_cov[g * 4096 + idx];
    for (int idx = tid; idx < 64 * CNY; idx += 256) {
        int i = idx >> 4, j = idx & 15;
        float s = 0.f;
#pragma unroll
        for (int sp = 0; sp < 8; ++sp) s += g_apart[sp][(g * 64 + i) * CNY + j];
        as[i][j] = s;
    }
    __syncthreads();
    float t = g_scal[1];
    int j = tid & 15, i0 = (tid >> 4) * 4;
#pragma unroll
    for (int ii = 0; ii < 4; ++ii) {
        float s = 0.f;
        for (int k = 0; k < 64; ++k) s = fmaf(covs[i0 + ii][k], as[k][j], s);
        w0s[i0 + ii][j] = t * s;
    }
    __syncthreads();
#pragma unroll
    for (int ii = 0; ii < 4; ++ii) {
        float s = 0.f;
        for (int k = 0; k < 64; ++k) s = fmaf(covs[i0 + ii][k], w0s[k][j], s);
        g_cw[(g * 64 + i0 + ii) * CNY + j] = s;
        g_w0[(g * 64 + i0 + ii) * CNY + j] = w0s[i0 + ii][j];
    }
}

// ---------------- softmax over groups ----------------
__global__ __launch_bounds__(1024) void k_p() {
    int tid = threadIdx.x;
    int g = tid >> 4, j = tid & 15;
    float corr = 0.f;
    for (int i = 0; i < 64; ++i)
        corr = fmaf(g_w0[(g * 64 + i) * CNY + j], g_cw[(g * 64 + i) * CNY + j], corr);
    float t = g_scal[1];
    float lg = corr - t * g_ycss[j] - g_S[g];
    __shared__ float L[64][17];
    __shared__ float mx[16], sm[16];
    L[g][j] = lg;
    __syncthreads();
    if (tid < 16) {
        float m = -1e30f;
        for (int gg = 0; gg < 64; ++gg) m = fmaxf(m, L[gg][tid]);
        float s = 0.f;
        for (int gg = 0; gg < 64; ++gg) s += expf(L[gg][tid] - m);
        mx[tid] = m; sm[tid] = s;
    }
    __syncthreads();
    g_p[g * CNY + j] = expf(lg - mx[j]) / sm[j];
}

// ---------------- fold xmul into w and cov (merged) ----------------
__global__ void k_fold() {
    int idx = blockIdx.x * 256 + threadIdx.x;
    if (idx < CNH * CNY) {
        int c = idx >> 4, j = idx & 15;
        g_w[idx] = g_w0[idx] * g_p[(c >> 6) * CNY + j] / g_xmul[c];
    }
    int g = idx >> 12, i = (idx >> 6) & 63, j = idx & 63;
    g_covv[idx] = g_cov[idx] / (g_xmul[g * 64 + i] * g_xmul[g * 64 + j]);
}

// ---------------- predict partials: groups split PSPLIT ways ----------------
__global__ __launch_bounds__(128) void k_predict_part(const float* __restrict__ XQ) {
    const int tid = threadIdx.x;
    const int r = tid >> 3, lane = tid & 7;
    const int row0 = blockIdx.x * 16;
    const int g0 = blockIdx.y * (CG / PSPLIT);
    __shared__ float Xs[16][65];
    __shared__ float Cs[64][65];
    __shared__ float Ws[64][17];
    __shared__ float ps[16];
    float accy[CNY] = {};
    float v0 = 0.f, v1 = 0.f;
    for (int g = g0; g < g0 + CG / PSPLIT; ++g) {
#pragma unroll
        for (int it = 0; it < 8; ++it) {
            int idx = tid + it * 128;
            Xs[idx >> 6][idx & 63] = XQ[(size_t)(row0 + (idx >> 6)) * CNH + g * 64 + (idx & 63)];
        }
#pragma unroll
        for (int it = 0; it < 32; ++it) {
            int idx = tid + it * 128;
            Cs[idx >> 6][idx & 63] = g_covv[g * 4096 + idx];
        }
#pragma unroll
        for (int it = 0; it < 8; ++it) {
            int idx = tid + it * 128;
            Ws[idx >> 4][idx & 15] = g_w[(g * 64 + (idx >> 4)) * CNY + (idx & 15)];
        }
        if (tid < 16) ps[tid] = g_p[g * CNY + tid];
        __syncthreads();
        float x[8];
#pragma unroll
        for (int ii = 0; ii < 8; ++ii) x[ii] = Xs[r][lane * 8 + ii];
#pragma unroll
        for (int ii = 0; ii < 8; ++ii)
#pragma unroll
            for (int j = 0; j < CNY; ++j)
                accy[j] = fmaf(x[ii], Ws[lane * 8 + ii][j], accy[j]);
        float s = 0.f;
        for (int jc = 0; jc < 64; ++jc) {
            float xj = Xs[r][jc];
            float q = 0.f;
#pragma unroll
            for (int ii = 0; ii < 8; ++ii) q = fmaf(Cs[lane * 8 + ii][jc], x[ii], q);
            s = fmaf(q, xj, s);
        }
        s += __shfl_xor_sync(0xffffffffu, s, 4);
        s += __shfl_xor_sync(0xffffffffu, s, 2);
        s += __shfl_xor_sync(0xffffffffu, s, 1);
        v0 = fmaf(s, ps[lane * 2 + 0], v0);
        v1 = fmaf(s, ps[lane * 2 + 1], v1);
        __syncthreads();
    }
#pragma unroll
    for (int j = 0; j < CNY; ++j) {
        accy[j] += __shfl_xor_sync(0xffffffffu, accy[j], 4);
        accy[j] += __shfl_xor_sync(0xffffffffu, accy[j], 2);
        accy[j] += __shfl_xor_sync(0xffffffffu, accy[j], 1);
    }
    const int row = row0 + r;
    const int j0 = lane * 2, j1 = j0 + 1;
    g_accp[blockIdx.y][row * CNY + j0] = accy[j0];
    g_accp[blockIdx.y][row * CNY + j1] = accy[j1];
    g_vp[blockIdx.y][row * CNY + j0] = v0;
    g_vp[blockIdx.y][row * CNY + j1] = v1;
}

// ---------------- predict combine ----------------
__global__ void k_predict_comb(float* __restrict__ out) {
    int idx = blockIdx.x * 256 + threadIdx.x;
    int j = idx & 15;
    float a = 0.f, v = 0.f;
#pragma unroll
    for (int s = 0; s < PSPLIT; ++s) { a += g_accp[s][idx]; v += g_vp[s][idx]; }
    out[idx] = (a + g_bmean[j]) * g_ymul[j];
    out[CN * CNY + idx] = sqrtf(fmaxf(v, 0.f)) * g_ymul[j];
}

// ---------------- launcher ----------------
extern "C" void kernel_launch(void* const* d_in, const int* in_sizes, int n_in,
                              void* d_out, int out_size) {
    const void* x  = d_in[0];
    const float* y = (const float*)d_in[1];
    const void* qx = d_in[2];
    const float* we = (const float*)d_in[3];
    const float* W1 = (const float*)d_in[4];
    const float* b1 = (const float*)d_in[5];
    const float* W2 = (const float*)d_in[6];
    const float* b2 = (const float*)d_in[7];
    const float* W3 = (const float*)d_in[8];
    const float* b3 = (const float*)d_in[9];
    const float* rp = (const float*)d_in[10];
    const float* tp = (const float*)d_in[11];
    float* out = (float*)d_out;

    __half *peh, *ph1h, *ph1l, *ph2h, *ph2l;
    __half *pW1h, *pW2h, *pW3h;
    float *pX;
    cudaGetSymbolAddress((void**)&peh,  g_eh);
    cudaGetSymbolAddress((void**)&ph1h, g_h1h);
    cudaGetSymbolAddress((void**)&ph1l, g_h1l);
    cudaGetSymbolAddress((void**)&ph2h, g_h2h);
    cudaGetSymbolAddress((void**)&ph2l, g_h2l);
    cudaGetSymbolAddress((void**)&pW1h, g_W1h);
    cudaGetSymbolAddress((void**)&pW2h, g_W2h);
    cudaGetSymbolAddress((void**)&pW3h, g_W3h);
    cudaGetSymbolAddress((void**)&pX,  g_X);
    float* pXQ = pX + (size_t)CN * CNH;

    const int SM64NL  = 2 * (64 * 64 + 8192);     // 24 KB (hi-only A, BM=64)
    const int SM64    = 2 * (64 * 128 + 8192);    // 32 KB (split A, BM=64)
    const int SM128NL = 2 * (128 * 64 + 8192);    // 32 KB (hi-only A, BM=128)
    cudaFuncSetAttribute((void*)k_gemm_fp16<64, false, 3>,  cudaFuncAttributeMaxDynamicSharedMemorySize, SM64NL);
    cudaFuncSetAttribute((void*)k_gemm_fp16<64, true, 2>,   cudaFuncAttributeMaxDynamicSharedMemorySize, SM64);
    cudaFuncSetAttribute((void*)k_gemm_fp16<128, false, 2>, cudaFuncAttributeMaxDynamicSharedMemorySize, SM128NL);

    // launches 1-3, captured launch (#4) is GEMM1
    k_detect<<<1, 256>>>((const int*)x, in_sizes[0]);
    k_wh<<<(NW1 + NW2 + NW3 + 255) / 256, 256>>>((const float4*)W1, (const float4*)W2, (const float4*)W3);
    const int gatherBlocks = (CN2 * (CNIN / 4) + 255) / 256;
    k_gather<<<gatherBlocks, 256>>>(x, qx, (const float4*)we, peh);

    k_gemm_fp16<64, false, 3><<<dim3(CH / 128, CN2 / 64), 256, SM64NL>>>(peh, nullptr, pW1h, b1, nullptr, ph1h, ph1l, CN2, CH, CNIN, 1);
    k_gemm_fp16<64, true, 2><<<dim3(CH / 128, CN2 / 64), 256, SM64>>>(ph1h, ph1l, pW2h, b2, nullptr, ph2h, ph2l, CN2, CH, CH, 1);
    k_gemm_fp16<128, false, 2><<<dim3(CNH / 128, CN2 / 128), 256, SM128NL>>>(ph2h, nullptr, pW3h, b3, pX, nullptr, nullptr, CN2, CNH, CH, 0);

    // ridge learn
    k_scal<<<1, 1>>>(rp, tp);
    k_ystats<<<16, 256>>>(y);
    k_xstats<<<CNH / 256, 256>>>();
    k_cov<<<dim3(CG, 4), 256>>>();
    k_apart<<<dim3(CNH / 256, 8), 256>>>();
    k_chol<<<CG, 64>>>();
    k_w0cw<<<CG, 256>>>();
    k_p<<<1, 1024>>>();
    k_fold<<<(CG * 64 * 64) / 256, 256>>>();

    // predict: group-split partials + combine
    k_predict_part<<<dim3(CN / 16, PSPLIT), 128>>>(pXQ);
    k_predict_comb<<<(CN * CNY) / 256, 256>>>(out);
}